// round 4
// baseline (speedup 1.0000x reference)
#include <cuda_runtime.h>
#include <cuda_bf16.h>

// AnomalyAttention, B=16 L=512 H=8 E=D=64, fp32.
// out[b,l,h,:] = gate/Se[l] * sum_{s<=l} exp(q.k/8) V[s]  (kernel A, flash-style)
//             + (1-gate)/Sg[l] * sum_{|l-s|<=16} 2^{-(l-s)^2 c} V[s]  (kernel B, banded prior)
// Exact-cancellation simplifications vs reference are all < 1e-7 relative.

typedef unsigned long long ull;

static __device__ __forceinline__ ull pk2(float a, float b) {
    ull r;
    asm("mov.b64 %0, {%1, %2};" : "=l"(r) : "f"(a), "f"(b));
    return r;
}
static __device__ __forceinline__ void fma2(ull& c, ull a, ull b) {
    asm("fma.rn.f32x2 %0, %1, %2, %0;" : "+l"(c) : "l"(a), "l"(b));
}
static __device__ __forceinline__ float2 upk(ull v) {
    float lo, hi;
    asm("mov.b64 {%0, %1}, %2;" : "=f"(lo), "=f"(hi) : "l"(v));
    return make_float2(lo, hi);
}

// ---------------------------------------------------------------------------
// Kernel A: causal softmax part. grid (rtile=4, bh=128), 128 threads.
// Row tile 128, s-tile 64. Per thread: 8x8 micro for both GEMMs (rows packed
// in f32x2 pairs). E round-trips through smem between QK and AV phases.
// smem (dynamic 96KB): Qt[64][128] kmajor, Kt[64][64] kmajor, Vs[64][64],
// Et[64][128] (s, l).
// ---------------------------------------------------------------------------
__global__ __launch_bounds__(128, 2)
void k_attn(const float* __restrict__ Qg, const float* __restrict__ Kg,
            const float* __restrict__ Vg, const float* __restrict__ hg,
            float* __restrict__ Og) {
    const int rtile = blockIdx.x;
    const int bh    = blockIdx.y;
    const int b = bh >> 3, h = bh & 7;
    const int tid = threadIdx.x;
    const int tx = tid & 7;        // col group
    const int ty = tid >> 3;       // row group (0..15)
    const int lbase = rtile * 128;

    extern __shared__ float sm[];
    float* Qt = sm;                 // 64*128
    float* Kt = sm + 8192;          // 64*64
    float* Vs = sm + 12288;         // 64*64
    float* Et = sm + 16384;         // 64*128

    // stage Q transposed (k-major)
    {
        const float* Qb = Qg + ((size_t)(b * 512 + lbase) * 8 + h) * 64;
        for (int idx = tid; idx < 2048; idx += 128) {
            int l = idx >> 4, kq = (idx & 15) << 2;
            float4 v = *(const float4*)(Qb + l * 512 + kq);
            Qt[(kq + 0) * 128 + l] = v.x;
            Qt[(kq + 1) * 128 + l] = v.y;
            Qt[(kq + 2) * 128 + l] = v.z;
            Qt[(kq + 3) * 128 + l] = v.w;
        }
    }

    ull acco[4][8];
#pragma unroll
    for (int rp = 0; rp < 4; rp++)
#pragma unroll
        for (int cj = 0; cj < 8; cj++) acco[rp][cj] = 0ull;
    float rsum[8] = {0.f, 0.f, 0.f, 0.f, 0.f, 0.f, 0.f, 0.f};

    const int ntiles = 2 * (rtile + 1);
    for (int st = 0; st < ntiles; st++) {
        const int s0 = st * 64;
        __syncthreads();  // protect Kt/Vs/Et reuse from previous AV phase
        // stage K (k-major transposed) and V (row-major)
        {
            const float* Kb = Kg + ((size_t)(b * 512 + s0) * 8 + h) * 64;
            const float* Vb = Vg + ((size_t)(b * 512 + s0) * 8 + h) * 64;
            for (int idx = tid; idx < 1024; idx += 128) {
                int s = idx >> 4, kq = (idx & 15) << 2;
                float4 v = *(const float4*)(Kb + s * 512 + kq);
                Kt[(kq + 0) * 64 + s] = v.x;
                Kt[(kq + 1) * 64 + s] = v.y;
                Kt[(kq + 2) * 64 + s] = v.z;
                Kt[(kq + 3) * 64 + s] = v.w;
                float4 w = *(const float4*)(Vb + s * 512 + kq);
                *(float4*)(Vs + s * 64 + kq) = w;
            }
        }
        __syncthreads();

        // ---- QK: S[128 l][64 s] ----
        ull acc[4][8];
#pragma unroll
        for (int rp = 0; rp < 4; rp++)
#pragma unroll
            for (int cj = 0; cj < 8; cj++) acc[rp][cj] = 0ull;

#pragma unroll 8
        for (int k = 0; k < 64; k++) {
            float4 qa = *(const float4*)(Qt + k * 128 + ty * 4);
            float4 qb = *(const float4*)(Qt + k * 128 + 64 + ty * 4);
            float4 ka = *(const float4*)(Kt + k * 64 + tx * 4);
            float4 kb = *(const float4*)(Kt + k * 64 + 32 + tx * 4);
            ull qp[4] = { pk2(qa.x, qa.y), pk2(qa.z, qa.w),
                          pk2(qb.x, qb.y), pk2(qb.z, qb.w) };
            float kk[8] = { ka.x, ka.y, ka.z, ka.w, kb.x, kb.y, kb.z, kb.w };
#pragma unroll
            for (int cj = 0; cj < 8; cj++) {
                ull kbb = pk2(kk[cj], kk[cj]);
#pragma unroll
                for (int rp = 0; rp < 4; rp++) fma2(acc[rp][cj], qp[rp], kbb);
            }
        }

        // ---- epilogue: masked exp -> Et, row sums ----
#pragma unroll
        for (int rp = 0; rp < 4; rp++) {
            int base = (rp < 2) ? (ty * 4 + rp * 2) : (64 + ty * 4 + (rp - 2) * 2);
#pragma unroll
            for (int cj = 0; cj < 8; cj++) {
                int sloc = (cj < 4) ? (tx * 4 + cj) : (32 + tx * 4 + (cj - 4));
                int s = s0 + sloc;
                float2 t = upk(acc[rp][cj]);
                int l0 = lbase + base;
                float e0 = (s <= l0)     ? __expf(t.x * 0.125f) : 0.f;
                float e1 = (s <= l0 + 1) ? __expf(t.y * 0.125f) : 0.f;
                rsum[rp * 2 + 0] += e0;
                rsum[rp * 2 + 1] += e1;
                *(float2*)(Et + sloc * 128 + base) = make_float2(e0, e1);
            }
        }
        __syncthreads();

        // ---- AV: O[128 l][64 d] += E . V ----
#pragma unroll 8
        for (int k = 0; k < 64; k++) {
            float4 ea = *(const float4*)(Et + k * 128 + ty * 4);
            float4 eb = *(const float4*)(Et + k * 128 + 64 + ty * 4);
            float4 va = *(const float4*)(Vs + k * 64 + tx * 4);
            float4 vb = *(const float4*)(Vs + k * 64 + 32 + tx * 4);
            ull ep[4] = { pk2(ea.x, ea.y), pk2(ea.z, ea.w),
                          pk2(eb.x, eb.y), pk2(eb.z, eb.w) };
            float vv[8] = { va.x, va.y, va.z, va.w, vb.x, vb.y, vb.z, vb.w };
#pragma unroll
            for (int cj = 0; cj < 8; cj++) {
                ull vbb = pk2(vv[cj], vv[cj]);
#pragma unroll
                for (int rp = 0; rp < 4; rp++) fma2(acco[rp][cj], ep[rp], vbb);
            }
        }
    }

    // reduce row sums across the 8 tx lanes sharing the same rows
#pragma unroll
    for (int o = 1; o < 8; o <<= 1)
#pragma unroll
        for (int i = 0; i < 8; i++)
            rsum[i] += __shfl_xor_sync(0xFFFFFFFFu, rsum[i], o);

    const float gate = 1.f / (1.f + __expf(-hg[h]));

#pragma unroll
    for (int rp = 0; rp < 4; rp++) {
        int base = (rp < 2) ? (ty * 4 + rp * 2) : (64 + ty * 4 + (rp - 2) * 2);
        float2 vals[8];
#pragma unroll
        for (int cj = 0; cj < 8; cj++) vals[cj] = upk(acco[rp][cj]);
#pragma unroll
        for (int w = 0; w < 2; w++) {
            int rloc = base + w;
            float sc = gate / rsum[rp * 2 + w];
            float4 oa, ob;
            oa.x = sc * (w ? vals[0].y : vals[0].x);
            oa.y = sc * (w ? vals[1].y : vals[1].x);
            oa.z = sc * (w ? vals[2].y : vals[2].x);
            oa.w = sc * (w ? vals[3].y : vals[3].x);
            ob.x = sc * (w ? vals[4].y : vals[4].x);
            ob.y = sc * (w ? vals[5].y : vals[5].x);
            ob.z = sc * (w ? vals[6].y : vals[6].x);
            ob.w = sc * (w ? vals[7].y : vals[7].x);
            float* orow = Og + ((size_t)(b * 512 + lbase + rloc) * 8 + h) * 64;
            *(float4*)(orow + tx * 4)      = oa;
            *(float4*)(orow + 32 + tx * 4) = ob;
        }
    }
}

// ---------------------------------------------------------------------------
// Kernel B: banded Gaussian prior, out += (1-gate)/Sg * sum_{|w|<=16} g(w) V[l+w].
// grid (ltile=4, bh=128), 128 threads (4 warps). One warp per row, 32 rows/warp,
// lanes along d (2 floats each). Gaussian by multiplicative recurrence
// (underflow-safe: all factors <= 1).
// ---------------------------------------------------------------------------
__global__ __launch_bounds__(128, 4)
void k_prior(const float* __restrict__ Vg, const float* __restrict__ Sig,
             const float* __restrict__ hg, float* __restrict__ Og) {
    const int ltile = blockIdx.x;
    const int bh    = blockIdx.y;
    const int b = bh >> 3, h = bh & 7;
    const int tid = threadIdx.x;
    const int warp = tid >> 5, lane = tid & 31;
    const int lbase = ltile * 128;

    __shared__ float Vb[160 * 64];  // rows lbase-16 .. lbase+143 (clipped -> 0)

    for (int idx = tid; idx < 160 * 16; idx += 128) {
        int r = idx >> 4, kq = (idx & 15) << 2;
        int sr = lbase - 16 + r;
        float4 v = make_float4(0.f, 0.f, 0.f, 0.f);
        if (sr >= 0 && sr < 512)
            v = *(const float4*)(Vg + ((size_t)(b * 512 + sr) * 8 + h) * 64 + kq);
        *(float4*)(Vb + r * 64 + kq) = v;
    }
    __syncthreads();

    const float og = 1.f - 1.f / (1.f + __expf(-hg[h]));

    for (int it = 0; it < 32; it++) {
        int row = warp * 32 + it;
        int l = lbase + row;

        float x   = Sig[((size_t)b * 512 + l) * 8 + h];
        float sgm = 1.f / (1.f + __expf(-5.f * x)) + 1e-5f;
        float sv  = exp2f(sgm * 1.5849625007211562f) - 1.f;  // 3^sgm - 1
        float c   = 1.4426950408889634f / (2.f * sv * sv);   // g(d)=2^{-d^2 c}

        float g  = 1.f;
        float rr = exp2f(-c);
        float q  = rr * rr;
        float Sg = 1.f;

        ull acc = *(const ull*)(Vb + (row + 16) * 64 + lane * 2);  // w=0, g=1

#pragma unroll
        for (int w = 1; w <= 16; w++) {
            g *= rr; rr *= q;  // g = 2^{-w^2 c}
            float gm = (l - w >= 0)  ? g : 0.f;
            float gp = (l + w < 512) ? g : 0.f;
            Sg += gm + gp;
            ull vm = *(const ull*)(Vb + (row + 16 - w) * 64 + lane * 2);
            ull vp = *(const ull*)(Vb + (row + 16 + w) * 64 + lane * 2);
            fma2(acc, vm, pk2(gm, gm));
            fma2(acc, vp, pk2(gp, gp));
        }

        float coef = og / Sg;
        float2 a = upk(acc);
        float* op = Og + ((size_t)(b * 512 + l) * 8 + h) * 64 + lane * 2;
        float2 cur = *(const float2*)op;
        cur.x += coef * a.x;
        cur.y += coef * a.y;
        *(float2*)op = cur;
    }
}

// ---------------------------------------------------------------------------
extern "C" void kernel_launch(void* const* d_in, const int* in_sizes, int n_in,
                              void* d_out, int out_size) {
    const float* Q   = (const float*)d_in[0];
    const float* K   = (const float*)d_in[1];
    const float* V   = (const float*)d_in[2];
    const float* Sig = (const float*)d_in[3];
    const float* hg  = (const float*)d_in[4];
    // d_in[5] = attn_mask (causal, known analytically) -- unused
    float* O = (float*)d_out;
    (void)in_sizes; (void)n_in; (void)out_size;

    cudaFuncSetAttribute(k_attn, cudaFuncAttributeMaxDynamicSharedMemorySize,
                         96 * 1024);

    dim3 gA(4, 128);
    k_attn<<<gA, 128, 96 * 1024>>>(Q, K, V, hg, O);

    dim3 gB(4, 128);
    k_prior<<<gB, 128>>>(V, Sig, hg, O);
}

// round 6
// speedup vs baseline: 1.2906x; 1.2906x over previous
#include <cuda_runtime.h>
#include <cuda_bf16.h>

// AnomalyAttention, B=16 L=512 H=8 E=D=64, fp32.
// out[b,l,h,:] = gate/Se[l] * sum_{s<=l} exp(q.k/8) V[s]         (k_attn, flash-style)
//             + (1-gate)/Sg[l] * sum_{|w|<=wmax} 2^{-w^2 c} V[l+w] (k_prior, banded)
// All algebraic simplifications vs the reference are < 1e-7 relative.
// R4: XOR-swizzled smem (kills 16-way staging / 8-way epilogue conflicts),
//     dynamic prior band (2^-24 cutoff), higher k_prior occupancy.

typedef unsigned long long ull;

static __device__ __forceinline__ ull pk2(float a, float b) {
    ull r;
    asm("mov.b64 %0, {%1, %2};" : "=l"(r) : "f"(a), "f"(b));
    return r;
}
static __device__ __forceinline__ void fma2(ull& c, ull a, ull b) {
    asm("fma.rn.f32x2 %0, %1, %2, %0;" : "+l"(c) : "l"(a), "l"(b));
}
static __device__ __forceinline__ float2 upk(ull v) {
    float lo, hi;
    asm("mov.b64 {%0, %1}, %2;" : "=f"(lo), "=f"(hi) : "l"(v));
    return make_float2(lo, hi);
}

// ---------------------------------------------------------------------------
// k_attn: causal softmax part. grid (rtile=4, bh=128), 128 threads.
// Row tile 128, s-tile 64, 8x8 microtile per thread (rows packed in f32x2).
// smem (96KB): Qt[64][128] k-major, Kt[64][64] k-major, Vs[64][64] row-major,
// Et[64 s][128 l]. Qt/Kt/Et columns XOR-swizzled at 4-float granularity with
// key = (k_row>>2)&7 so transpose-writes are ~2-way and reads conflict-free.
// ---------------------------------------------------------------------------
__global__ __launch_bounds__(128, 2)
void k_attn(const float* __restrict__ Qg, const float* __restrict__ Kg,
            const float* __restrict__ Vg, const float* __restrict__ hg,
            float* __restrict__ Og) {
    const int rtile = blockIdx.x;
    const int bh    = blockIdx.y;
    const int b = bh >> 3, h = bh & 7;
    const int tid = threadIdx.x;
    const int tx = tid & 7;        // col group (8)
    const int ty = tid >> 3;       // row group (16)
    const int lbase = rtile * 128;

    extern __shared__ float sm[];
    float* Qt = sm;                 // 64*128
    float* Kt = sm + 8192;          // 64*64
    float* Vs = sm + 12288;         // 64*64
    float* Et = sm + 16384;         // 64*128

    // stage Q transposed, swizzled: row k, phys col = ((l>>2)^((k>>2)&7))<<2 | (l&3)
    {
        const float* Qb = Qg + ((size_t)(b * 512 + lbase) * 8 + h) * 64;
        for (int idx = tid; idx < 2048; idx += 128) {
            int l = idx >> 4, kq4 = idx & 15;
            float4 v = *(const float4*)(Qb + l * 512 + (kq4 << 2));
            int pcol = (((l >> 2) ^ (kq4 & 7)) << 2) | (l & 3);
            float* dst = Qt + (kq4 << 2) * 128 + pcol;
            dst[0]   = v.x;
            dst[128] = v.y;
            dst[256] = v.z;
            dst[384] = v.w;
        }
    }

    ull acco[4][8];
#pragma unroll
    for (int rp = 0; rp < 4; rp++)
#pragma unroll
        for (int cj = 0; cj < 8; cj++) acco[rp][cj] = 0ull;
    float rsum[8] = {0.f, 0.f, 0.f, 0.f, 0.f, 0.f, 0.f, 0.f};

    const int ntiles = 2 * (rtile + 1);
    for (int st = 0; st < ntiles; st++) {
        const int s0 = st * 64;
        __syncthreads();  // protect Kt/Vs/Et from previous iteration readers
        // stage K (k-major, swizzled) and V (row-major)
        {
            const float* Kb = Kg + ((size_t)(b * 512 + s0) * 8 + h) * 64;
            const float* Vb = Vg + ((size_t)(b * 512 + s0) * 8 + h) * 64;
            for (int idx = tid; idx < 1024; idx += 128) {
                int s = idx >> 4, kq4 = idx & 15;
                float4 v = *(const float4*)(Kb + s * 512 + (kq4 << 2));
                int pcol = (((s >> 2) ^ (kq4 & 7)) << 2) | (s & 3);
                float* dst = Kt + (kq4 << 2) * 64 + pcol;
                dst[0]   = v.x;
                dst[64]  = v.y;
                dst[128] = v.z;
                dst[192] = v.w;
                float4 w = *(const float4*)(Vb + s * 512 + (kq4 << 2));
                *(float4*)(Vs + s * 64 + (kq4 << 2)) = w;
            }
        }
        __syncthreads();

        // ---- QK: S[128 l][64 s] ----
        ull acc[4][8];
#pragma unroll
        for (int rp = 0; rp < 4; rp++)
#pragma unroll
            for (int cj = 0; cj < 8; cj++) acc[rp][cj] = 0ull;

#pragma unroll 8
        for (int k = 0; k < 64; k++) {
            const int key = (k >> 2) & 7;
            const float* qrow = Qt + k * 128;
            const float* krow = Kt + k * 64;
            const int qo = (ty ^ key) << 2;
            const int ko = (tx ^ key) << 2;
            float4 qa = *(const float4*)(qrow + qo);
            float4 qb = *(const float4*)(qrow + 64 + qo);
            float4 ka = *(const float4*)(krow + ko);
            float4 kb = *(const float4*)(krow + 32 + ko);
            ull qp[4] = { pk2(qa.x, qa.y), pk2(qa.z, qa.w),
                          pk2(qb.x, qb.y), pk2(qb.z, qb.w) };
            float kk[8] = { ka.x, ka.y, ka.z, ka.w, kb.x, kb.y, kb.z, kb.w };
#pragma unroll
            for (int cj = 0; cj < 8; cj++) {
                ull kbb = pk2(kk[cj], kk[cj]);
#pragma unroll
                for (int rp = 0; rp < 4; rp++) fma2(acc[rp][cj], qp[rp], kbb);
            }
        }

        // ---- epilogue: masked exp -> Et (swizzled), row sums ----
#pragma unroll
        for (int rp = 0; rp < 4; rp++) {
            int base = (rp < 2) ? (ty * 4 + rp * 2) : (64 + ty * 4 + (rp - 2) * 2);
            int c4b = base >> 2;
            int boff = base & 3;
#pragma unroll
            for (int cj = 0; cj < 8; cj++) {
                int sloc = (cj < 4) ? (tx * 4 + cj) : (32 + tx * 4 + (cj - 4));
                int s = s0 + sloc;
                float2 t = upk(acc[rp][cj]);
                int l0 = lbase + base;
                float e0 = (s <= l0)     ? __expf(t.x * 0.125f) : 0.f;
                float e1 = (s <= l0 + 1) ? __expf(t.y * 0.125f) : 0.f;
                rsum[rp * 2 + 0] += e0;
                rsum[rp * 2 + 1] += e1;
                int pcol = (((c4b ^ ((sloc >> 2) & 7)) << 2) | boff);
                *(float2*)(Et + sloc * 128 + pcol) = make_float2(e0, e1);
            }
        }
        __syncthreads();

        // ---- AV: O[128 l][64 d] += E . V ----
#pragma unroll 8
        for (int k = 0; k < 64; k++) {
            const int key = (k >> 2) & 7;
            const float* erow = Et + k * 128;
            const int eo = (ty ^ key) << 2;
            float4 ea = *(const float4*)(erow + eo);
            float4 eb = *(const float4*)(erow + 64 + eo);
            float4 va = *(const float4*)(Vs + k * 64 + tx * 4);
            float4 vb = *(const float4*)(Vs + k * 64 + 32 + tx * 4);
            ull ep[4] = { pk2(ea.x, ea.y), pk2(ea.z, ea.w),
                          pk2(eb.x, eb.y), pk2(eb.z, eb.w) };
            float vv[8] = { va.x, va.y, va.z, va.w, vb.x, vb.y, vb.z, vb.w };
#pragma unroll
            for (int cj = 0; cj < 8; cj++) {
                ull vbb = pk2(vv[cj], vv[cj]);
#pragma unroll
                for (int rp = 0; rp < 4; rp++) fma2(acco[rp][cj], ep[rp], vbb);
            }
        }
    }

    // reduce row sums across the 8 tx lanes sharing the same rows
#pragma unroll
    for (int o = 1; o < 8; o <<= 1)
#pragma unroll
        for (int i = 0; i < 8; i++)
            rsum[i] += __shfl_xor_sync(0xFFFFFFFFu, rsum[i], o);

    const float gate = 1.f / (1.f + __expf(-hg[h]));

#pragma unroll
    for (int rp = 0; rp < 4; rp++) {
        int base = (rp < 2) ? (ty * 4 + rp * 2) : (64 + ty * 4 + (rp - 2) * 2);
        float2 vals[8];
#pragma unroll
        for (int cj = 0; cj < 8; cj++) vals[cj] = upk(acco[rp][cj]);
#pragma unroll
        for (int w = 0; w < 2; w++) {
            int rloc = base + w;
            float sc = gate / rsum[rp * 2 + w];
            float4 oa, ob;
            oa.x = sc * (w ? vals[0].y : vals[0].x);
            oa.y = sc * (w ? vals[1].y : vals[1].x);
            oa.z = sc * (w ? vals[2].y : vals[2].x);
            oa.w = sc * (w ? vals[3].y : vals[3].x);
            ob.x = sc * (w ? vals[4].y : vals[4].x);
            ob.y = sc * (w ? vals[5].y : vals[5].x);
            ob.z = sc * (w ? vals[6].y : vals[6].x);
            ob.w = sc * (w ? vals[7].y : vals[7].x);
            float* orow = Og + ((size_t)(b * 512 + lbase + rloc) * 8 + h) * 64;
            *(float4*)(orow + tx * 4)      = oa;
            *(float4*)(orow + 32 + tx * 4) = ob;
        }
    }
}

// ---------------------------------------------------------------------------
// k_prior: banded Gaussian prior, out += (1-gate)/Sg * sum_w g(w) V[l+w].
// grid (ltile=8, bh=128), 128 threads (4 warps), 16 rows/warp, 64 rows/block.
// Dynamic band: g(w)=2^{-w^2 c} < 2^-24 terms dropped (w_max <= 12 always,
// typically ~5). Two accumulators break the FMA dependence chain.
// smem 24KB -> ~9 blocks/SM.
// ---------------------------------------------------------------------------
__global__ __launch_bounds__(128, 8)
void k_prior(const float* __restrict__ Vg, const float* __restrict__ Sig,
             const float* __restrict__ hg, float* __restrict__ Og) {
    const int ltile = blockIdx.x;        // 0..7
    const int bh    = blockIdx.y;
    const int b = bh >> 3, h = bh & 7;
    const int tid = threadIdx.x;
    const int warp = tid >> 5, lane = tid & 31;
    const int lbase = ltile * 64;

    __shared__ float Vb[96 * 64];  // rows lbase-16 .. lbase+79 (clipped -> 0)

    for (int idx = tid; idx < 96 * 16; idx += 128) {
        int r = idx >> 4, kq = (idx & 15) << 2;
        int sr = lbase - 16 + r;
        float4 v = make_float4(0.f, 0.f, 0.f, 0.f);
        if (sr >= 0 && sr < 512)
            v = *(const float4*)(Vg + ((size_t)(b * 512 + sr) * 8 + h) * 64 + kq);
        *(float4*)(Vb + r * 64 + kq) = v;
    }
    __syncthreads();

    const float og = 1.f - 1.f / (1.f + __expf(-hg[h]));

    for (int it = 0; it < 16; it++) {
        int row = warp * 16 + it;
        int l = lbase + row;

        float x   = Sig[((size_t)b * 512 + l) * 8 + h];
        float sgm = 1.f / (1.f + __expf(-5.f * x)) + 1e-5f;
        float sv  = exp2f(sgm * 1.5849625007211562f) - 1.f;  // 3^sgm - 1
        float c   = 1.4426950408889634f / (2.f * sv * sv);   // g(w)=2^{-w^2 c}

        int wmax = (int)sqrtf(24.f / c);
        if (wmax > 16) wmax = 16;

        float g  = 1.f;
        float rr = exp2f(-c);
        float q  = rr * rr;
        float SgA = 1.f, SgB = 0.f;

        ull accA = *(const ull*)(Vb + (row + 16) * 64 + lane * 2);  // w=0, g=1
        ull accB = 0ull;

        for (int w = 1; w <= wmax; w++) {
            g *= rr; rr *= q;  // g = 2^{-w^2 c}
            float gm = (l - w >= 0)  ? g : 0.f;
            float gp = (l + w < 512) ? g : 0.f;
            SgA += gm; SgB += gp;
            ull vm = *(const ull*)(Vb + (row + 16 - w) * 64 + lane * 2);
            ull vp = *(const ull*)(Vb + (row + 16 + w) * 64 + lane * 2);
            fma2(accA, vm, pk2(gm, gm));
            fma2(accB, vp, pk2(gp, gp));
        }

        float coef = og / (SgA + SgB);
        float2 a = upk(accA);
        float2 bb = upk(accB);
        float* op = Og + ((size_t)(b * 512 + l) * 8 + h) * 64 + lane * 2;
        float2 cur = *(const float2*)op;
        cur.x += coef * (a.x + bb.x);
        cur.y += coef * (a.y + bb.y);
        *(float2*)op = cur;
    }
}

// ---------------------------------------------------------------------------
extern "C" void kernel_launch(void* const* d_in, const int* in_sizes, int n_in,
                              void* d_out, int out_size) {
    const float* Q   = (const float*)d_in[0];
    const float* K   = (const float*)d_in[1];
    const float* V   = (const float*)d_in[2];
    const float* Sig = (const float*)d_in[3];
    const float* hg  = (const float*)d_in[4];
    // d_in[5] = attn_mask (causal, known analytically) -- unused
    float* O = (float*)d_out;
    (void)in_sizes; (void)n_in; (void)out_size;

    cudaFuncSetAttribute(k_attn, cudaFuncAttributeMaxDynamicSharedMemorySize,
                         96 * 1024);

    dim3 gA(4, 128);
    k_attn<<<gA, 128, 96 * 1024>>>(Q, K, V, hg, O);

    dim3 gB(8, 128);
    k_prior<<<gB, 128>>>(V, Sig, hg, O);
}

// round 8
// speedup vs baseline: 2.1751x; 1.6853x over previous
#include <cuda_runtime.h>
#include <cuda_bf16.h>
#include <cstdint>

// AnomalyAttention, B=16 L=512 H=8 E=D=64, fp32 in/out.
// k_attn_mma: legacy mma.sync bf16 split-precision flash attention (causal).
//   S = Qh.Kh^T + Qh.Kl^T + Ql.Kh^T   (3-term bf16 split, ~2^-16)
//   O = Eh.Vh   + Eh.Vl   + El.Vh     (E built from S in REGISTERS:
//                                      C-fragment == A-fragment layout)
// k_prior: banded Gaussian prior (unchanged, known good).

typedef unsigned long long ull;

// swizzled smem address: 128B rows, XOR row bits into byte bits [4:6]
#define SWB(row, byte) (((row) << 7) + ((byte) ^ (((row) & 7) << 4)))

// pack two fp32 -> bf16x2, 'lo' in low half
static __device__ __forceinline__ uint32_t pkbf2(float lo, float hi) {
    uint32_t r;
    asm("cvt.rn.bf16x2.f32 %0, %1, %2;" : "=r"(r) : "f"(hi), "f"(lo));
    return r;
}
static __device__ __forceinline__ float bf_lo_f(uint32_t p) {
    __nv_bfloat162 t = *reinterpret_cast<__nv_bfloat162*>(&p);
    return __bfloat162float(t.x);
}
static __device__ __forceinline__ float bf_hi_f(uint32_t p) {
    __nv_bfloat162 t = *reinterpret_cast<__nv_bfloat162*>(&p);
    return __bfloat162float(t.y);
}
static __device__ __forceinline__ void mma_bf16(float* c, const uint32_t* a,
                                                const uint32_t* b) {
    asm volatile(
        "mma.sync.aligned.m16n8k16.row.col.f32.bf16.bf16.f32 "
        "{%0,%1,%2,%3}, {%4,%5,%6,%7}, {%8,%9}, {%0,%1,%2,%3};"
        : "+f"(c[0]), "+f"(c[1]), "+f"(c[2]), "+f"(c[3])
        : "r"(a[0]), "r"(a[1]), "r"(a[2]), "r"(a[3]), "r"(b[0]), "r"(b[1]));
}

// smem offsets (bytes): Qh/Ql [128 rows][128B], Kh/Kl [64][128B], Vh/Vl [64][128B]
#define OFF_QH 0
#define OFF_QL 16384
#define OFF_KH 32768
#define OFF_KL 40960
#define OFF_VH 49152
#define OFF_VL 57344
#define SMEM_BYTES 65536

// ---------------------------------------------------------------------------
// k_attn_mma: grid (4 rtile, 128 bh), 256 threads (8 warps, 16 rows each).
// ---------------------------------------------------------------------------
__global__ __launch_bounds__(256)
void k_attn_mma(const float* __restrict__ Qg, const float* __restrict__ Kg,
                const float* __restrict__ Vg, const float* __restrict__ hg,
                float* __restrict__ Og) {
    extern __shared__ char smc[];
    char* Qh_ = smc + OFF_QH;
    char* Ql_ = smc + OFF_QL;
    char* Kh_ = smc + OFF_KH;
    char* Kl_ = smc + OFF_KL;
    char* Vh_ = smc + OFF_VH;
    char* Vl_ = smc + OFF_VL;

    const int rtile = 3 - blockIdx.x;  // heavy blocks first
    const int bh = blockIdx.y;
    const int b = bh >> 3, h = bh & 7;
    const int tid = threadIdx.x;
    const int wid = tid >> 5, lane = tid & 31;
    const int g = lane >> 2, t = lane & 3;
    const int lbase = rtile * 128;
    const int wr = wid * 16;           // warp's row offset within the 128-tile

    // ---- stage Q once: bf16 hi/lo split, [l][e] rows, swizzled ----
    {
        const float* Qb = Qg + ((size_t)(b * 512 + lbase) * 8 + h) * 64;
        for (int idx = tid; idx < 2048; idx += 256) {
            int l = idx >> 4, e4 = (idx & 15) << 2;
            float4 v = *(const float4*)(Qb + l * 512 + e4);
            uint32_t h0 = pkbf2(v.x, v.y), h1 = pkbf2(v.z, v.w);
            uint32_t l0 = pkbf2(v.x - bf_lo_f(h0), v.y - bf_hi_f(h0));
            uint32_t l1 = pkbf2(v.z - bf_lo_f(h1), v.w - bf_hi_f(h1));
            int sa = SWB(l, e4 * 2);
            *(uint2*)(Qh_ + sa) = make_uint2(h0, h1);
            *(uint2*)(Ql_ + sa) = make_uint2(l0, l1);
        }
    }

    float accO[8][4];
#pragma unroll
    for (int nt = 0; nt < 8; nt++)
#pragma unroll
        for (int i = 0; i < 4; i++) accO[nt][i] = 0.f;
    float rs0 = 0.f, rs1 = 0.f;

    const int ntiles = 2 * rtile + 2;
    for (int st = 0; st < ntiles; st++) {
        const int s0 = st * 64;
        __syncthreads();  // previous tile's readers done
        // ---- stage K [s][e] and V transposed [d][s], hi/lo split ----
        {
            const float* Kb = Kg + ((size_t)(b * 512 + s0) * 8 + h) * 64;
            for (int idx = tid; idx < 1024; idx += 256) {
                int s = idx >> 4, e4 = (idx & 15) << 2;
                float4 v = *(const float4*)(Kb + s * 512 + e4);
                uint32_t h0 = pkbf2(v.x, v.y), h1 = pkbf2(v.z, v.w);
                uint32_t l0 = pkbf2(v.x - bf_lo_f(h0), v.y - bf_hi_f(h0));
                uint32_t l1 = pkbf2(v.z - bf_lo_f(h1), v.w - bf_hi_f(h1));
                int sa = SWB(s, e4 * 2);
                *(uint2*)(Kh_ + sa) = make_uint2(h0, h1);
                *(uint2*)(Kl_ + sa) = make_uint2(l0, l1);
            }
            const float* Vb = Vg + ((size_t)(b * 512 + s0) * 8 + h) * 64;
            for (int idx = tid; idx < 512; idx += 256) {
                int sp = idx >> 4, dq = idx & 15;
                int s = sp * 2, d4 = dq * 4;
                float4 v0 = *(const float4*)(Vb + s * 512 + d4);
                float4 v1 = *(const float4*)(Vb + (s + 1) * 512 + d4);
                float a0[4] = {v0.x, v0.y, v0.z, v0.w};
                float a1[4] = {v1.x, v1.y, v1.z, v1.w};
#pragma unroll
                for (int j = 0; j < 4; j++) {
                    uint32_t hp = pkbf2(a0[j], a1[j]);
                    uint32_t lp = pkbf2(a0[j] - bf_lo_f(hp), a1[j] - bf_hi_f(hp));
                    int sa = SWB(d4 + j, sp * 4);
                    *(uint32_t*)(Vh_ + sa) = hp;
                    *(uint32_t*)(Vl_ + sa) = lp;
                }
            }
        }
        __syncthreads();

        // ---- QK: S[16 l][64 s] per warp via m16n8k16 ----
        float accS[8][4];
#pragma unroll
        for (int nt = 0; nt < 8; nt++)
#pragma unroll
            for (int i = 0; i < 4; i++) accS[nt][i] = 0.f;

#pragma unroll
        for (int k = 0; k < 4; k++) {
            const int kb = k * 32 + t * 4;
            const int r0 = wr + g, r1 = wr + g + 8;
            uint32_t aQh[4], aQl[4];
            aQh[0] = *(uint32_t*)(Qh_ + SWB(r0, kb));
            aQh[1] = *(uint32_t*)(Qh_ + SWB(r1, kb));
            aQh[2] = *(uint32_t*)(Qh_ + SWB(r0, kb + 16));
            aQh[3] = *(uint32_t*)(Qh_ + SWB(r1, kb + 16));
            aQl[0] = *(uint32_t*)(Ql_ + SWB(r0, kb));
            aQl[1] = *(uint32_t*)(Ql_ + SWB(r1, kb));
            aQl[2] = *(uint32_t*)(Ql_ + SWB(r0, kb + 16));
            aQl[3] = *(uint32_t*)(Ql_ + SWB(r1, kb + 16));
#pragma unroll
            for (int nt = 0; nt < 8; nt++) {
                const int rb = nt * 8 + g;
                uint32_t bKh[2], bKl[2];
                bKh[0] = *(uint32_t*)(Kh_ + SWB(rb, kb));
                bKh[1] = *(uint32_t*)(Kh_ + SWB(rb, kb + 16));
                bKl[0] = *(uint32_t*)(Kl_ + SWB(rb, kb));
                bKl[1] = *(uint32_t*)(Kl_ + SWB(rb, kb + 16));
                mma_bf16(accS[nt], aQh, bKh);
                mma_bf16(accS[nt], aQh, bKl);
                mma_bf16(accS[nt], aQl, bKh);
            }
        }

        // ---- mask + exp in registers, row sums ----
        const int row0 = lbase + wr + g, row1 = row0 + 8;
#pragma unroll
        for (int nt = 0; nt < 8; nt++) {
            const int c0 = s0 + nt * 8 + t * 2;
            float e0 = (c0     <= row0) ? __expf(accS[nt][0] * 0.125f) : 0.f;
            float e1 = (c0 + 1 <= row0) ? __expf(accS[nt][1] * 0.125f) : 0.f;
            float e2 = (c0     <= row1) ? __expf(accS[nt][2] * 0.125f) : 0.f;
            float e3 = (c0 + 1 <= row1) ? __expf(accS[nt][3] * 0.125f) : 0.f;
            rs0 += e0 + e1;
            rs1 += e2 + e3;
            accS[nt][0] = e0; accS[nt][1] = e1;
            accS[nt][2] = e2; accS[nt][3] = e3;
        }

        // ---- EV: O += E.V, E as A-fragments straight from registers ----
#pragma unroll
        for (int kk = 0; kk < 4; kk++) {
            const int n0 = 2 * kk, n1 = 2 * kk + 1;
            uint32_t eh[4], el[4];
            eh[0] = pkbf2(accS[n0][0], accS[n0][1]);
            eh[1] = pkbf2(accS[n0][2], accS[n0][3]);
            eh[2] = pkbf2(accS[n1][0], accS[n1][1]);
            eh[3] = pkbf2(accS[n1][2], accS[n1][3]);
            el[0] = pkbf2(accS[n0][0] - bf_lo_f(eh[0]), accS[n0][1] - bf_hi_f(eh[0]));
            el[1] = pkbf2(accS[n0][2] - bf_lo_f(eh[1]), accS[n0][3] - bf_hi_f(eh[1]));
            el[2] = pkbf2(accS[n1][0] - bf_lo_f(eh[2]), accS[n1][1] - bf_hi_f(eh[2]));
            el[3] = pkbf2(accS[n1][2] - bf_lo_f(eh[3]), accS[n1][3] - bf_hi_f(eh[3]));
            const int kb = kk * 32 + t * 4;
#pragma unroll
            for (int nt = 0; nt < 8; nt++) {
                const int rd = nt * 8 + g;
                uint32_t bVh[2], bVl[2];
                bVh[0] = *(uint32_t*)(Vh_ + SWB(rd, kb));
                bVh[1] = *(uint32_t*)(Vh_ + SWB(rd, kb + 16));
                bVl[0] = *(uint32_t*)(Vl_ + SWB(rd, kb));
                bVl[1] = *(uint32_t*)(Vl_ + SWB(rd, kb + 16));
                mma_bf16(accO[nt], eh, bVh);
                mma_bf16(accO[nt], eh, bVl);
                mma_bf16(accO[nt], el, bVh);
            }
        }
    }

    // ---- row-sum reduce over the 4 lanes of each group, scale, store ----
    rs0 += __shfl_xor_sync(0xFFFFFFFFu, rs0, 1);
    rs0 += __shfl_xor_sync(0xFFFFFFFFu, rs0, 2);
    rs1 += __shfl_xor_sync(0xFFFFFFFFu, rs1, 1);
    rs1 += __shfl_xor_sync(0xFFFFFFFFu, rs1, 2);

    const float gate = 1.f / (1.f + __expf(-hg[h]));
    const float sc0 = gate / rs0, sc1 = gate / rs1;
    const int row0 = lbase + wr + g, row1 = row0 + 8;
    float* o0 = Og + ((size_t)(b * 512 + row0) * 8 + h) * 64;
    float* o1 = Og + ((size_t)(b * 512 + row1) * 8 + h) * 64;
#pragma unroll
    for (int nt = 0; nt < 8; nt++) {
        const int d = nt * 8 + t * 2;
        *(float2*)(o0 + d) = make_float2(sc0 * accO[nt][0], sc0 * accO[nt][1]);
        *(float2*)(o1 + d) = make_float2(sc1 * accO[nt][2], sc1 * accO[nt][3]);
    }
}

// ---------------------------------------------------------------------------
// k_prior: banded Gaussian prior (unchanged from R5, known good, ~30us).
// ---------------------------------------------------------------------------
static __device__ __forceinline__ ull pk2s(float a, float b) {
    ull r;
    asm("mov.b64 %0, {%1, %2};" : "=l"(r) : "f"(a), "f"(b));
    return r;
}
static __device__ __forceinline__ void fma2(ull& c, ull a, ull b) {
    asm("fma.rn.f32x2 %0, %1, %2, %0;" : "+l"(c) : "l"(a), "l"(b));
}
static __device__ __forceinline__ float2 upk(ull v) {
    float lo, hi;
    asm("mov.b64 {%0, %1}, %2;" : "=f"(lo), "=f"(hi) : "l"(v));
    return make_float2(lo, hi);
}

__global__ __launch_bounds__(128, 8)
void k_prior(const float* __restrict__ Vg, const float* __restrict__ Sig,
             const float* __restrict__ hg, float* __restrict__ Og) {
    const int ltile = blockIdx.x;
    const int bh    = blockIdx.y;
    const int b = bh >> 3, h = bh & 7;
    const int tid = threadIdx.x;
    const int warp = tid >> 5, lane = tid & 31;
    const int lbase = ltile * 64;

    __shared__ float Vb[96 * 64];

    for (int idx = tid; idx < 96 * 16; idx += 128) {
        int r = idx >> 4, kq = (idx & 15) << 2;
        int sr = lbase - 16 + r;
        float4 v = make_float4(0.f, 0.f, 0.f, 0.f);
        if (sr >= 0 && sr < 512)
            v = *(const float4*)(Vg + ((size_t)(b * 512 + sr) * 8 + h) * 64 + kq);
        *(float4*)(Vb + r * 64 + kq) = v;
    }
    __syncthreads();

    const float og = 1.f - 1.f / (1.f + __expf(-hg[h]));

    for (int it = 0; it < 16; it++) {
        int row = warp * 16 + it;
        int l = lbase + row;

        float x   = Sig[((size_t)b * 512 + l) * 8 + h];
        float sgm = 1.f / (1.f + __expf(-5.f * x)) + 1e-5f;
        float sv  = exp2f(sgm * 1.5849625007211562f) - 1.f;
        float c   = 1.4426950408889634f / (2.f * sv * sv);

        int wmax = (int)sqrtf(24.f / c);
        if (wmax > 16) wmax = 16;

        float gg = 1.f;
        float rr = exp2f(-c);
        float q  = rr * rr;
        float SgA = 1.f, SgB = 0.f;

        ull accA = *(const ull*)(Vb + (row + 16) * 64 + lane * 2);
        ull accB = 0ull;

        for (int w = 1; w <= wmax; w++) {
            gg *= rr; rr *= q;
            float gm = (l - w >= 0)  ? gg : 0.f;
            float gp = (l + w < 512) ? gg : 0.f;
            SgA += gm; SgB += gp;
            ull vm = *(const ull*)(Vb + (row + 16 - w) * 64 + lane * 2);
            ull vp = *(const ull*)(Vb + (row + 16 + w) * 64 + lane * 2);
            fma2(accA, vm, pk2s(gm, gm));
            fma2(accB, vp, pk2s(gp, gp));
        }

        float coef = og / (SgA + SgB);
        float2 a = upk(accA);
        float2 bb = upk(accB);
        float* op = Og + ((size_t)(b * 512 + l) * 8 + h) * 64 + lane * 2;
        float2 cur = *(const float2*)op;
        cur.x += coef * (a.x + bb.x);
        cur.y += coef * (a.y + bb.y);
        *(float2*)op = cur;
    }
}

// ---------------------------------------------------------------------------
extern "C" void kernel_launch(void* const* d_in, const int* in_sizes, int n_in,
                              void* d_out, int out_size) {
    const float* Q   = (const float*)d_in[0];
    const float* K   = (const float*)d_in[1];
    const float* V   = (const float*)d_in[2];
    const float* Sig = (const float*)d_in[3];
    const float* hg  = (const float*)d_in[4];
    float* O = (float*)d_out;
    (void)in_sizes; (void)n_in; (void)out_size;

    cudaFuncSetAttribute(k_attn_mma, cudaFuncAttributeMaxDynamicSharedMemorySize,
                         SMEM_BYTES);

    dim3 gA(4, 128);
    k_attn_mma<<<gA, 256, SMEM_BYTES>>>(Q, K, V, hg, O);

    dim3 gB(8, 128);
    k_prior<<<gB, 128>>>(V, Sig, hg, O);
}

// round 9
// speedup vs baseline: 2.1973x; 1.0102x over previous
#include <cuda_runtime.h>
#include <cuda_bf16.h>
#include <cstdint>

// AnomalyAttention, B=16 L=512 H=8 E=D=64, fp32 in/out. Single fused kernel.
// out = (gate/Se) * [ E.V  +  G''.V ]   per row, where
//   E   = exp(Q.K^T/8) causal (3-term bf16-split HMMA),
//   G'' = (Se*og)/(gate*Sg) * exp2(-(l-s)^2 c)  (prior folded into same
//         accumulator AFTER Se is known; banded +-16 so only ~5 kk-chunks/warp).
// All algebraic simplifications vs reference < 1e-7; bf16 splits ~2^-16.

// swizzled smem address: 128B rows, XOR row bits into byte bits [4:6]
#define SWB(row, byte) (((row) << 7) + ((byte) ^ (((row) & 7) << 4)))

static __device__ __forceinline__ uint32_t pkbf2(float lo, float hi) {
    uint32_t r;
    asm("cvt.rn.bf16x2.f32 %0, %1, %2;" : "=r"(r) : "f"(hi), "f"(lo));
    return r;
}
static __device__ __forceinline__ float bf_lo_f(uint32_t p) {
    __nv_bfloat162 t = *reinterpret_cast<__nv_bfloat162*>(&p);
    return __bfloat162float(t.x);
}
static __device__ __forceinline__ float bf_hi_f(uint32_t p) {
    __nv_bfloat162 t = *reinterpret_cast<__nv_bfloat162*>(&p);
    return __bfloat162float(t.y);
}
static __device__ __forceinline__ void mma_bf16(float* c, const uint32_t* a,
                                                const uint32_t* b) {
    asm volatile(
        "mma.sync.aligned.m16n8k16.row.col.f32.bf16.bf16.f32 "
        "{%0,%1,%2,%3}, {%4,%5,%6,%7}, {%8,%9}, {%0,%1,%2,%3};"
        : "+f"(c[0]), "+f"(c[1]), "+f"(c[2]), "+f"(c[3])
        : "r"(a[0]), "r"(a[1]), "r"(a[2]), "r"(a[3]), "r"(b[0]), "r"(b[1]));
}

// smem offsets (bytes)
#define OFF_QH 0
#define OFF_QL 16384
#define OFF_KH 32768
#define OFF_KL 40960
#define OFF_VH 49152
#define OFF_VL 57344
#define SMEM_BYTES 65536

__global__ __launch_bounds__(256)
void k_fused(const float* __restrict__ Qg, const float* __restrict__ Kg,
             const float* __restrict__ Vg, const float* __restrict__ Sig,
             const float* __restrict__ hg, float* __restrict__ Og) {
    extern __shared__ char smc[];
    char* Qh_ = smc + OFF_QH;
    char* Ql_ = smc + OFF_QL;
    char* Kh_ = smc + OFF_KH;
    char* Kl_ = smc + OFF_KL;
    char* Vh_ = smc + OFF_VH;
    char* Vl_ = smc + OFF_VL;

    const int rtile = 3 - blockIdx.x;  // heavy blocks first
    const int bh = blockIdx.y;
    const int b = bh >> 3, h = bh & 7;
    const int tid = threadIdx.x;
    const int wid = tid >> 5, lane = tid & 31;
    const int g = lane >> 2, t = lane & 3;
    const int lbase = rtile * 128;
    const int wr = wid * 16;
    const int row0 = lbase + wr + g, row1 = row0 + 8;

    // ---- per-lane prior constants for its two rows ----
    float c0, c1, iSg0, iSg1;
    {
#pragma unroll
        for (int rr_ = 0; rr_ < 2; rr_++) {
            int l = rr_ ? row1 : row0;
            float x = Sig[((size_t)(b * 512 + l)) * 8 + h];
            float sgm = 1.f / (1.f + __expf(-5.f * x)) + 1e-5f;
            float sv = exp2f(sgm * 1.5849625007211562f) - 1.f;  // 3^sgm - 1
            float c = 1.4426950408889634f / (2.f * sv * sv);    // g=2^{-d^2 c}
            int wmax = (int)sqrtf(24.f / c);
            if (wmax > 16) wmax = 16;
            float gg = 1.f, rq = exp2f(-c), q = rq * rq, S = 1.f;
            for (int w = 1; w <= wmax; w++) {
                gg *= rq; rq *= q;
                if (l - w >= 0)  S += gg;
                if (l + w < 512) S += gg;
            }
            if (rr_) { c1 = c; iSg1 = 1.f / S; }
            else     { c0 = c; iSg0 = 1.f / S; }
        }
    }

    // ---- stage Q once: bf16 hi/lo split, [l][e] rows, swizzled ----
    {
        const float* Qb = Qg + ((size_t)(b * 512 + lbase) * 8 + h) * 64;
        for (int idx = tid; idx < 2048; idx += 256) {
            int l = idx >> 4, e4 = (idx & 15) << 2;
            float4 v = *(const float4*)(Qb + l * 512 + e4);
            uint32_t h0 = pkbf2(v.x, v.y), h1 = pkbf2(v.z, v.w);
            uint32_t l0 = pkbf2(v.x - bf_lo_f(h0), v.y - bf_hi_f(h0));
            uint32_t l1 = pkbf2(v.z - bf_lo_f(h1), v.w - bf_hi_f(h1));
            int sa = SWB(l, e4 * 2);
            *(uint2*)(Qh_ + sa) = make_uint2(h0, h1);
            *(uint2*)(Ql_ + sa) = make_uint2(l0, l1);
        }
    }

    float accO[8][4];
#pragma unroll
    for (int nt = 0; nt < 8; nt++)
#pragma unroll
        for (int i = 0; i < 4; i++) accO[nt][i] = 0.f;
    float rs0 = 0.f, rs1 = 0.f;

    const int ntiles = 2 * rtile + 2;
    for (int st = 0; st < ntiles; st++) {
        const int s0 = st * 64;
        __syncthreads();
        // ---- stage K [s][e] and V transposed [d][s], hi/lo split ----
        {
            const float* Kb = Kg + ((size_t)(b * 512 + s0) * 8 + h) * 64;
            for (int idx = tid; idx < 1024; idx += 256) {
                int s = idx >> 4, e4 = (idx & 15) << 2;
                float4 v = *(const float4*)(Kb + s * 512 + e4);
                uint32_t h0 = pkbf2(v.x, v.y), h1 = pkbf2(v.z, v.w);
                uint32_t l0 = pkbf2(v.x - bf_lo_f(h0), v.y - bf_hi_f(h0));
                uint32_t l1 = pkbf2(v.z - bf_lo_f(h1), v.w - bf_hi_f(h1));
                int sa = SWB(s, e4 * 2);
                *(uint2*)(Kh_ + sa) = make_uint2(h0, h1);
                *(uint2*)(Kl_ + sa) = make_uint2(l0, l1);
            }
            const float* Vb = Vg + ((size_t)(b * 512 + s0) * 8 + h) * 64;
            for (int idx = tid; idx < 512; idx += 256) {
                int sp = idx >> 4, dq = idx & 15;
                int s = sp * 2, d4 = dq * 4;
                float4 v0 = *(const float4*)(Vb + s * 512 + d4);
                float4 v1 = *(const float4*)(Vb + (s + 1) * 512 + d4);
                float a0[4] = {v0.x, v0.y, v0.z, v0.w};
                float a1[4] = {v1.x, v1.y, v1.z, v1.w};
#pragma unroll
                for (int j = 0; j < 4; j++) {
                    uint32_t hp = pkbf2(a0[j], a1[j]);
                    uint32_t lp = pkbf2(a0[j] - bf_lo_f(hp), a1[j] - bf_hi_f(hp));
                    int sa = SWB(d4 + j, sp * 4);
                    *(uint32_t*)(Vh_ + sa) = hp;
                    *(uint32_t*)(Vl_ + sa) = lp;
                }
            }
        }
        __syncthreads();

        // ---- QK: S[16 l][64 s] per warp via m16n8k16 ----
        float accS[8][4];
#pragma unroll
        for (int nt = 0; nt < 8; nt++)
#pragma unroll
            for (int i = 0; i < 4; i++) accS[nt][i] = 0.f;

#pragma unroll
        for (int k = 0; k < 4; k++) {
            const int kb = k * 32 + t * 4;
            const int r0 = wr + g, r1 = wr + g + 8;
            uint32_t aQh[4], aQl[4];
            aQh[0] = *(uint32_t*)(Qh_ + SWB(r0, kb));
            aQh[1] = *(uint32_t*)(Qh_ + SWB(r1, kb));
            aQh[2] = *(uint32_t*)(Qh_ + SWB(r0, kb + 16));
            aQh[3] = *(uint32_t*)(Qh_ + SWB(r1, kb + 16));
            aQl[0] = *(uint32_t*)(Ql_ + SWB(r0, kb));
            aQl[1] = *(uint32_t*)(Ql_ + SWB(r1, kb));
            aQl[2] = *(uint32_t*)(Ql_ + SWB(r0, kb + 16));
            aQl[3] = *(uint32_t*)(Ql_ + SWB(r1, kb + 16));
#pragma unroll
            for (int nt = 0; nt < 8; nt++) {
                const int rb = nt * 8 + g;
                uint32_t bKh[2], bKl[2];
                bKh[0] = *(uint32_t*)(Kh_ + SWB(rb, kb));
                bKh[1] = *(uint32_t*)(Kh_ + SWB(rb, kb + 16));
                bKl[0] = *(uint32_t*)(Kl_ + SWB(rb, kb));
                bKl[1] = *(uint32_t*)(Kl_ + SWB(rb, kb + 16));
                mma_bf16(accS[nt], aQh, bKh);
                mma_bf16(accS[nt], aQh, bKl);
                mma_bf16(accS[nt], aQl, bKh);
            }
        }

        // ---- mask + exp in registers, row sums ----
#pragma unroll
        for (int nt = 0; nt < 8; nt++) {
            const int c0_ = s0 + nt * 8 + t * 2;
            float e0 = (c0_     <= row0) ? __expf(accS[nt][0] * 0.125f) : 0.f;
            float e1 = (c0_ + 1 <= row0) ? __expf(accS[nt][1] * 0.125f) : 0.f;
            float e2 = (c0_     <= row1) ? __expf(accS[nt][2] * 0.125f) : 0.f;
            float e3 = (c0_ + 1 <= row1) ? __expf(accS[nt][3] * 0.125f) : 0.f;
            rs0 += e0 + e1;
            rs1 += e2 + e3;
            accS[nt][0] = e0; accS[nt][1] = e1;
            accS[nt][2] = e2; accS[nt][3] = e3;
        }

        // ---- EV: O += E.V, E as A-fragments straight from registers ----
#pragma unroll
        for (int kk = 0; kk < 4; kk++) {
            const int n0 = 2 * kk, n1 = 2 * kk + 1;
            uint32_t eh[4], el[4];
            eh[0] = pkbf2(accS[n0][0], accS[n0][1]);
            eh[1] = pkbf2(accS[n0][2], accS[n0][3]);
            eh[2] = pkbf2(accS[n1][0], accS[n1][1]);
            eh[3] = pkbf2(accS[n1][2], accS[n1][3]);
            el[0] = pkbf2(accS[n0][0] - bf_lo_f(eh[0]), accS[n0][1] - bf_hi_f(eh[0]));
            el[1] = pkbf2(accS[n0][2] - bf_lo_f(eh[1]), accS[n0][3] - bf_hi_f(eh[1]));
            el[2] = pkbf2(accS[n1][0] - bf_lo_f(eh[2]), accS[n1][1] - bf_hi_f(eh[2]));
            el[3] = pkbf2(accS[n1][2] - bf_lo_f(eh[3]), accS[n1][3] - bf_hi_f(eh[3]));
            const int kb = kk * 32 + t * 4;
#pragma unroll
            for (int nt = 0; nt < 8; nt++) {
                const int rd = nt * 8 + g;
                uint32_t bVh[2], bVl[2];
                bVh[0] = *(uint32_t*)(Vh_ + SWB(rd, kb));
                bVh[1] = *(uint32_t*)(Vh_ + SWB(rd, kb + 16));
                bVl[0] = *(uint32_t*)(Vl_ + SWB(rd, kb));
                bVl[1] = *(uint32_t*)(Vl_ + SWB(rd, kb + 16));
                mma_bf16(accO[nt], eh, bVh);
                mma_bf16(accO[nt], eh, bVl);
                mma_bf16(accO[nt], el, bVh);
            }
        }
    }

    // ---- row-sum reduce (Se now known) ----
    rs0 += __shfl_xor_sync(0xFFFFFFFFu, rs0, 1);
    rs0 += __shfl_xor_sync(0xFFFFFFFFu, rs0, 2);
    rs1 += __shfl_xor_sync(0xFFFFFFFFu, rs1, 1);
    rs1 += __shfl_xor_sync(0xFFFFFFFFu, rs1, 2);

    const float gate = 1.f / (1.f + __expf(-hg[h]));
    const float og = 1.f - gate;
    // G'' row factors: (Se/gate)*og/Sg  (final gate/Se scale then yields og/Sg)
    const float f0 = rs0 * og * iSg0 / gate;
    const float f1 = rs1 * og * iSg1 / gate;

    // ---- prior phase: accO += G''.V over band tiles (+-16 around diagonal) ----
    {
        const int ptlo = (rtile == 0) ? 0 : (2 * rtile - 1);
        const int pthi = (2 * rtile + 2 > 7) ? 7 : (2 * rtile + 2);
        const int wb0 = lbase + wr - 16;        // warp band s-range (inclusive)
        const int wb1 = lbase + wr + 15 + 16;
        for (int pt = ptlo; pt <= pthi; pt++) {
            const int s0 = pt * 64;
            __syncthreads();
            // stage V only
            {
                const float* Vb = Vg + ((size_t)(b * 512 + s0) * 8 + h) * 64;
                for (int idx = tid; idx < 512; idx += 256) {
                    int sp = idx >> 4, dq = idx & 15;
                    int s = sp * 2, d4 = dq * 4;
                    float4 v0 = *(const float4*)(Vb + s * 512 + d4);
                    float4 v1 = *(const float4*)(Vb + (s + 1) * 512 + d4);
                    float a0[4] = {v0.x, v0.y, v0.z, v0.w};
                    float a1[4] = {v1.x, v1.y, v1.z, v1.w};
#pragma unroll
                    for (int j = 0; j < 4; j++) {
                        uint32_t hp = pkbf2(a0[j], a1[j]);
                        uint32_t lp = pkbf2(a0[j] - bf_lo_f(hp), a1[j] - bf_hi_f(hp));
                        int sa = SWB(d4 + j, sp * 4);
                        *(uint32_t*)(Vh_ + sa) = hp;
                        *(uint32_t*)(Vl_ + sa) = lp;
                    }
                }
            }
            __syncthreads();

#pragma unroll
            for (int kk = 0; kk < 4; kk++) {
                const int ks0 = s0 + kk * 16;
                if (ks0 + 15 < wb0 || ks0 > wb1) continue;  // warp-uniform
                const int ca = ks0 + 2 * t, cb = ca + 8;
                float d;
                d = (float)(row0 - ca);       float a00 = f0 * exp2f(-d * d * c0);
                d = (float)(row0 - ca - 1);   float a01 = f0 * exp2f(-d * d * c0);
                d = (float)(row1 - ca);       float a10 = f1 * exp2f(-d * d * c1);
                d = (float)(row1 - ca - 1);   float a11 = f1 * exp2f(-d * d * c1);
                d = (float)(row0 - cb);       float a20 = f0 * exp2f(-d * d * c0);
                d = (float)(row0 - cb - 1);   float a21 = f0 * exp2f(-d * d * c0);
                d = (float)(row1 - cb);       float a30 = f1 * exp2f(-d * d * c1);
                d = (float)(row1 - cb - 1);   float a31 = f1 * exp2f(-d * d * c1);
                uint32_t gh[4], gl[4];
                gh[0] = pkbf2(a00, a01);
                gh[1] = pkbf2(a10, a11);
                gh[2] = pkbf2(a20, a21);
                gh[3] = pkbf2(a30, a31);
                gl[0] = pkbf2(a00 - bf_lo_f(gh[0]), a01 - bf_hi_f(gh[0]));
                gl[1] = pkbf2(a10 - bf_lo_f(gh[1]), a11 - bf_hi_f(gh[1]));
                gl[2] = pkbf2(a20 - bf_lo_f(gh[2]), a21 - bf_hi_f(gh[2]));
                gl[3] = pkbf2(a30 - bf_lo_f(gh[3]), a31 - bf_hi_f(gh[3]));
                const int kb = kk * 32 + t * 4;
#pragma unroll
                for (int nt = 0; nt < 8; nt++) {
                    const int rd = nt * 8 + g;
                    uint32_t bVh[2], bVl[2];
                    bVh[0] = *(uint32_t*)(Vh_ + SWB(rd, kb));
                    bVh[1] = *(uint32_t*)(Vh_ + SWB(rd, kb + 16));
                    bVl[0] = *(uint32_t*)(Vl_ + SWB(rd, kb));
                    bVl[1] = *(uint32_t*)(Vl_ + SWB(rd, kb + 16));
                    mma_bf16(accO[nt], gh, bVh);
                    mma_bf16(accO[nt], gh, bVl);
                    mma_bf16(accO[nt], gl, bVh);
                }
            }
        }
    }

    // ---- scale by gate/Se, store ----
    const float sc0 = gate / rs0, sc1 = gate / rs1;
    float* o0 = Og + ((size_t)(b * 512 + row0) * 8 + h) * 64;
    float* o1 = Og + ((size_t)(b * 512 + row1) * 8 + h) * 64;
#pragma unroll
    for (int nt = 0; nt < 8; nt++) {
        const int dd = nt * 8 + t * 2;
        *(float2*)(o0 + dd) = make_float2(sc0 * accO[nt][0], sc0 * accO[nt][1]);
        *(float2*)(o1 + dd) = make_float2(sc1 * accO[nt][2], sc1 * accO[nt][3]);
    }
}

// ---------------------------------------------------------------------------
extern "C" void kernel_launch(void* const* d_in, const int* in_sizes, int n_in,
                              void* d_out, int out_size) {
    const float* Q   = (const float*)d_in[0];
    const float* K   = (const float*)d_in[1];
    const float* V   = (const float*)d_in[2];
    const float* Sig = (const float*)d_in[3];
    const float* hg  = (const float*)d_in[4];
    float* O = (float*)d_out;
    (void)in_sizes; (void)n_in; (void)out_size;

    cudaFuncSetAttribute(k_fused, cudaFuncAttributeMaxDynamicSharedMemorySize,
                         SMEM_BYTES);

    dim3 gA(4, 128);
    k_fused<<<gA, 256, SMEM_BYTES>>>(Q, K, V, Sig, hg, O);
}

// round 10
// speedup vs baseline: 2.3094x; 1.0510x over previous
#include <cuda_runtime.h>
#include <cuda_bf16.h>
#include <cstdint>

// AnomalyAttention, B=16 L=512 H=8 E=D=64, fp32 in/out. Single fused kernel.
// out = (gate/Se) * [ E.V + G''.V ] per row;
//   E   = exp(Q.K^T/8) causal, 3-term bf16-split HMMA
//   G'' = (Se*og)/(gate*Sg) * 2^{-(l-s)^2 c}, banded +-16, folded post-Se.
// R9: cp.async double-buffered raw staging (hides global latency under MMAs),
//     warp-uniform causal chunk skipping (-17.5% MMA/LDS/exp),
//     prior reuses last resident V tile.

// swizzled smem address: 128B rows, XOR row bits into byte bits [4:6]
#define SWB(row, byte) (((row) << 7) + ((byte) ^ (((row) & 7) << 4)))

static __device__ __forceinline__ uint32_t pkbf2(float lo, float hi) {
    uint32_t r;
    asm("cvt.rn.bf16x2.f32 %0, %1, %2;" : "=r"(r) : "f"(hi), "f"(lo));
    return r;
}
static __device__ __forceinline__ float bf_lo_f(uint32_t p) {
    __nv_bfloat162 t = *reinterpret_cast<__nv_bfloat162*>(&p);
    return __bfloat162float(t.x);
}
static __device__ __forceinline__ float bf_hi_f(uint32_t p) {
    __nv_bfloat162 t = *reinterpret_cast<__nv_bfloat162*>(&p);
    return __bfloat162float(t.y);
}
static __device__ __forceinline__ void mma_bf16(float* c, const uint32_t* a,
                                                const uint32_t* b) {
    asm volatile(
        "mma.sync.aligned.m16n8k16.row.col.f32.bf16.bf16.f32 "
        "{%0,%1,%2,%3}, {%4,%5,%6,%7}, {%8,%9}, {%0,%1,%2,%3};"
        : "+f"(c[0]), "+f"(c[1]), "+f"(c[2]), "+f"(c[3])
        : "r"(a[0]), "r"(a[1]), "r"(a[2]), "r"(a[3]), "r"(b[0]), "r"(b[1]));
}
static __device__ __forceinline__ void cpasync16(uint32_t dst, const void* src) {
    asm volatile("cp.async.cg.shared.global [%0], [%1], 16;"
                 :: "r"(dst), "l"(src) : "memory");
}

// smem offsets (bytes)
#define OFF_QH 0
#define OFF_QL 16384
#define OFF_KH 32768
#define OFF_KL 40960
#define OFF_VH 49152
#define OFF_VL 57344
#define OFF_KRAW 65536
#define OFF_VRAW 81920
#define SMEM_BYTES 98304

__global__ __launch_bounds__(256)
void k_fused(const float* __restrict__ Qg, const float* __restrict__ Kg,
             const float* __restrict__ Vg, const float* __restrict__ Sig,
             const float* __restrict__ hg, float* __restrict__ Og) {
    extern __shared__ char smc[];
    char* Qh_ = smc + OFF_QH;
    char* Ql_ = smc + OFF_QL;
    char* Kh_ = smc + OFF_KH;
    char* Kl_ = smc + OFF_KL;
    char* Vh_ = smc + OFF_VH;
    char* Vl_ = smc + OFF_VL;
    const float* Kraw = (const float*)(smc + OFF_KRAW);
    const float* Vraw = (const float*)(smc + OFF_VRAW);

    uint32_t smb;
    asm("{ .reg .u64 t; cvta.to.shared.u64 t, %1; cvt.u32.u64 %0, t; }"
        : "=r"(smb) : "l"(smc));
    const uint32_t kraw32 = smb + OFF_KRAW;
    const uint32_t vraw32 = smb + OFF_VRAW;

    const int rtile = 3 - blockIdx.x;  // heavy blocks first
    const int bh = blockIdx.y;
    const int b = bh >> 3, h = bh & 7;
    const int tid = threadIdx.x;
    const int wid = tid >> 5, lane = tid & 31;
    const int g = lane >> 2, t = lane & 3;
    const int lbase = rtile * 128;
    const int wr = wid * 16;
    const int row0 = lbase + wr + g, row1 = row0 + 8;
    const int wlast = lbase + wr + 15;  // warp's last (largest) row

    // ---- per-lane prior constants ----
    float c0, c1, iSg0, iSg1;
    {
#pragma unroll
        for (int rr_ = 0; rr_ < 2; rr_++) {
            int l = rr_ ? row1 : row0;
            float x = Sig[((size_t)(b * 512 + l)) * 8 + h];
            float sgm = 1.f / (1.f + __expf(-5.f * x)) + 1e-5f;
            float sv = exp2f(sgm * 1.5849625007211562f) - 1.f;  // 3^sgm - 1
            float c = 1.4426950408889634f / (2.f * sv * sv);
            int wmax = (int)sqrtf(24.f / c);
            if (wmax > 16) wmax = 16;
            float gg = 1.f, rq = exp2f(-c), q = rq * rq, S = 1.f;
            for (int w = 1; w <= wmax; w++) {
                gg *= rq; rq *= q;
                if (l - w >= 0)  S += gg;
                if (l + w < 512) S += gg;
            }
            if (rr_) { c1 = c; iSg1 = 1.f / S; }
            else     { c0 = c; iSg0 = 1.f / S; }
        }
    }

    // ---- stage Q once: bf16 hi/lo split, swizzled ----
    {
        const float* Qb = Qg + ((size_t)(b * 512 + lbase) * 8 + h) * 64;
        for (int idx = tid; idx < 2048; idx += 256) {
            int l = idx >> 4, e4 = (idx & 15) << 2;
            float4 v = *(const float4*)(Qb + l * 512 + e4);
            uint32_t h0 = pkbf2(v.x, v.y), h1 = pkbf2(v.z, v.w);
            uint32_t l0 = pkbf2(v.x - bf_lo_f(h0), v.y - bf_hi_f(h0));
            uint32_t l1 = pkbf2(v.z - bf_lo_f(h1), v.w - bf_hi_f(h1));
            int sa = SWB(l, e4 * 2);
            *(uint2*)(Qh_ + sa) = make_uint2(h0, h1);
            *(uint2*)(Ql_ + sa) = make_uint2(l0, l1);
        }
    }

    float accO[8][4];
#pragma unroll
    for (int nt = 0; nt < 8; nt++)
#pragma unroll
        for (int i = 0; i < 4; i++) accO[nt][i] = 0.f;
    float rs0 = 0.f, rs1 = 0.f;

    const int ntiles = 2 * rtile + 2;

    // prefetch tile 0 (raw fp32 K/V via cp.async)
    {
        const float* Kb = Kg + ((size_t)(b * 512) * 8 + h) * 64 + (size_t)0;
        const float* Vb = Vg + ((size_t)(b * 512) * 8 + h) * 64 + (size_t)0;
        for (int idx = tid; idx < 1024; idx += 256) {
            int s = idx >> 4, cc = (idx & 15) << 2;
            cpasync16(kraw32 + idx * 16, Kb + s * 512 + cc);
            cpasync16(vraw32 + idx * 16, Vb + s * 512 + cc);
        }
        asm volatile("cp.async.commit_group;" ::: "memory");
    }

    for (int st = 0; st < ntiles; st++) {
        const int s0 = st * 64;
        asm volatile("cp.async.wait_group 0;" ::: "memory");
        __syncthreads();  // raw(st) ready; prev tile consumers done

        // ---- convert raw -> split smem (K: [s][e], V: transposed [d][s]) ----
        for (int idx = tid; idx < 1024; idx += 256) {
            int s = idx >> 4, e4 = (idx & 15) << 2;
            float4 v = *(const float4*)(Kraw + idx * 4);
            uint32_t h0 = pkbf2(v.x, v.y), h1 = pkbf2(v.z, v.w);
            uint32_t l0 = pkbf2(v.x - bf_lo_f(h0), v.y - bf_hi_f(h0));
            uint32_t l1 = pkbf2(v.z - bf_lo_f(h1), v.w - bf_hi_f(h1));
            int sa = SWB(s, e4 * 2);
            *(uint2*)(Kh_ + sa) = make_uint2(h0, h1);
            *(uint2*)(Kl_ + sa) = make_uint2(l0, l1);
        }
        for (int idx = tid; idx < 512; idx += 256) {
            int sp = idx >> 4, dq = idx & 15;
            int s = sp * 2, d4 = dq * 4;
            float4 v0 = *(const float4*)(Vraw + s * 64 + d4);
            float4 v1 = *(const float4*)(Vraw + (s + 1) * 64 + d4);
            float a0[4] = {v0.x, v0.y, v0.z, v0.w};
            float a1[4] = {v1.x, v1.y, v1.z, v1.w};
#pragma unroll
            for (int j = 0; j < 4; j++) {
                uint32_t hp = pkbf2(a0[j], a1[j]);
                uint32_t lp = pkbf2(a0[j] - bf_lo_f(hp), a1[j] - bf_hi_f(hp));
                int sa = SWB(d4 + j, sp * 4);
                *(uint32_t*)(Vh_ + sa) = hp;
                *(uint32_t*)(Vl_ + sa) = lp;
            }
        }
        __syncthreads();  // split ready; raw free for next prefetch

        // ---- prefetch next tile during MMA phase ----
        if (st + 1 < ntiles) {
            const int sn = (st + 1) * 64;
            const float* Kb = Kg + ((size_t)(b * 512 + sn) * 8 + h) * 64;
            const float* Vb = Vg + ((size_t)(b * 512 + sn) * 8 + h) * 64;
            for (int idx = tid; idx < 1024; idx += 256) {
                int s = idx >> 4, cc = (idx & 15) << 2;
                cpasync16(kraw32 + idx * 16, Kb + s * 512 + cc);
                cpasync16(vraw32 + idx * 16, Vb + s * 512 + cc);
            }
            asm volatile("cp.async.commit_group;" ::: "memory");
        }

        if (s0 > wlast) continue;  // whole tile masked for this warp

        // ---- QK: S[16 l][64 s], skip fully-masked nt chunks ----
        float accS[8][4];
#pragma unroll
        for (int nt = 0; nt < 8; nt++)
#pragma unroll
            for (int i = 0; i < 4; i++) accS[nt][i] = 0.f;

#pragma unroll
        for (int k = 0; k < 4; k++) {
            const int kb = k * 32 + t * 4;
            const int r0 = wr + g, r1 = wr + g + 8;
            uint32_t aQh[4], aQl[4];
            aQh[0] = *(uint32_t*)(Qh_ + SWB(r0, kb));
            aQh[1] = *(uint32_t*)(Qh_ + SWB(r1, kb));
            aQh[2] = *(uint32_t*)(Qh_ + SWB(r0, kb + 16));
            aQh[3] = *(uint32_t*)(Qh_ + SWB(r1, kb + 16));
            aQl[0] = *(uint32_t*)(Ql_ + SWB(r0, kb));
            aQl[1] = *(uint32_t*)(Ql_ + SWB(r1, kb));
            aQl[2] = *(uint32_t*)(Ql_ + SWB(r0, kb + 16));
            aQl[3] = *(uint32_t*)(Ql_ + SWB(r1, kb + 16));
#pragma unroll
            for (int nt = 0; nt < 8; nt++) {
                if (s0 + nt * 8 > wlast) continue;  // warp-uniform
                const int rb = nt * 8 + g;
                uint32_t bKh[2], bKl[2];
                bKh[0] = *(uint32_t*)(Kh_ + SWB(rb, kb));
                bKh[1] = *(uint32_t*)(Kh_ + SWB(rb, kb + 16));
                bKl[0] = *(uint32_t*)(Kl_ + SWB(rb, kb));
                bKl[1] = *(uint32_t*)(Kl_ + SWB(rb, kb + 16));
                mma_bf16(accS[nt], aQh, bKh);
                mma_bf16(accS[nt], aQh, bKl);
                mma_bf16(accS[nt], aQl, bKh);
            }
        }

        // ---- mask + exp, row sums (skip masked chunks) ----
#pragma unroll
        for (int nt = 0; nt < 8; nt++) {
            if (s0 + nt * 8 > wlast) continue;
            const int c0_ = s0 + nt * 8 + t * 2;
            float e0 = (c0_     <= row0) ? __expf(accS[nt][0] * 0.125f) : 0.f;
            float e1 = (c0_ + 1 <= row0) ? __expf(accS[nt][1] * 0.125f) : 0.f;
            float e2 = (c0_     <= row1) ? __expf(accS[nt][2] * 0.125f) : 0.f;
            float e3 = (c0_ + 1 <= row1) ? __expf(accS[nt][3] * 0.125f) : 0.f;
            rs0 += e0 + e1;
            rs1 += e2 + e3;
            accS[nt][0] = e0; accS[nt][1] = e1;
            accS[nt][2] = e2; accS[nt][3] = e3;
        }

        // ---- EV: O += E.V (skip fully-masked kk chunks) ----
#pragma unroll
        for (int kk = 0; kk < 4; kk++) {
            if (s0 + kk * 16 > wlast) continue;  // warp-uniform
            const int n0 = 2 * kk, n1 = 2 * kk + 1;
            uint32_t eh[4], el[4];
            eh[0] = pkbf2(accS[n0][0], accS[n0][1]);
            eh[1] = pkbf2(accS[n0][2], accS[n0][3]);
            eh[2] = pkbf2(accS[n1][0], accS[n1][1]);
            eh[3] = pkbf2(accS[n1][2], accS[n1][3]);
            el[0] = pkbf2(accS[n0][0] - bf_lo_f(eh[0]), accS[n0][1] - bf_hi_f(eh[0]));
            el[1] = pkbf2(accS[n0][2] - bf_lo_f(eh[1]), accS[n0][3] - bf_hi_f(eh[1]));
            el[2] = pkbf2(accS[n1][0] - bf_lo_f(eh[2]), accS[n1][1] - bf_hi_f(eh[2]));
            el[3] = pkbf2(accS[n1][2] - bf_lo_f(eh[3]), accS[n1][3] - bf_hi_f(eh[3]));
            const int kb = kk * 32 + t * 4;
#pragma unroll
            for (int nt = 0; nt < 8; nt++) {
                const int rd = nt * 8 + g;
                uint32_t bVh[2], bVl[2];
                bVh[0] = *(uint32_t*)(Vh_ + SWB(rd, kb));
                bVh[1] = *(uint32_t*)(Vh_ + SWB(rd, kb + 16));
                bVl[0] = *(uint32_t*)(Vl_ + SWB(rd, kb));
                bVl[1] = *(uint32_t*)(Vl_ + SWB(rd, kb + 16));
                mma_bf16(accO[nt], eh, bVh);
                mma_bf16(accO[nt], eh, bVl);
                mma_bf16(accO[nt], el, bVh);
            }
        }
    }

    // ---- row-sum reduce (Se now known) ----
    rs0 += __shfl_xor_sync(0xFFFFFFFFu, rs0, 1);
    rs0 += __shfl_xor_sync(0xFFFFFFFFu, rs0, 2);
    rs1 += __shfl_xor_sync(0xFFFFFFFFu, rs1, 1);
    rs1 += __shfl_xor_sync(0xFFFFFFFFu, rs1, 2);

    const float gate = 1.f / (1.f + __expf(-hg[h]));
    const float og = 1.f - gate;
    const float f0 = rs0 * og * iSg0 / gate;
    const float f1 = rs1 * og * iSg1 / gate;

    // ---- prior phase: accO += G''.V over band tiles; first tile is resident ----
    {
        int pts[4];
        int np = 0;
        pts[np++] = 2 * rtile + 1;            // V already staged (last main tile)
        if (2 * rtile - 1 >= 0) pts[np++] = 2 * rtile - 1;
        pts[np++] = 2 * rtile;
        if (2 * rtile + 2 <= 7) pts[np++] = 2 * rtile + 2;

        const int wb0 = lbase + wr - 16;
        const int wb1 = lbase + wr + 15 + 16;

        for (int pi = 0; pi < np; pi++) {
            const int pt = pts[pi];
            const int s0 = pt * 64;
            if (pi > 0) {
                __syncthreads();
                const float* Vb = Vg + ((size_t)(b * 512 + s0) * 8 + h) * 64;
                for (int idx = tid; idx < 512; idx += 256) {
                    int sp = idx >> 4, dq = idx & 15;
                    int s = sp * 2, d4 = dq * 4;
                    float4 v0 = *(const float4*)(Vb + s * 512 + d4);
                    float4 v1 = *(const float4*)(Vb + (s + 1) * 512 + d4);
                    float a0[4] = {v0.x, v0.y, v0.z, v0.w};
                    float a1[4] = {v1.x, v1.y, v1.z, v1.w};
#pragma unroll
                    for (int j = 0; j < 4; j++) {
                        uint32_t hp = pkbf2(a0[j], a1[j]);
                        uint32_t lp = pkbf2(a0[j] - bf_lo_f(hp), a1[j] - bf_hi_f(hp));
                        int sa = SWB(d4 + j, sp * 4);
                        *(uint32_t*)(Vh_ + sa) = hp;
                        *(uint32_t*)(Vl_ + sa) = lp;
                    }
                }
                __syncthreads();
            }

#pragma unroll
            for (int kk = 0; kk < 4; kk++) {
                const int ks0 = s0 + kk * 16;
                if (ks0 + 15 < wb0 || ks0 > wb1) continue;  // warp-uniform
                const int ca = ks0 + 2 * t, cb = ca + 8;
                float d;
                d = (float)(row0 - ca);       float a00 = f0 * exp2f(-d * d * c0);
                d = (float)(row0 - ca - 1);   float a01 = f0 * exp2f(-d * d * c0);
                d = (float)(row1 - ca);       float a10 = f1 * exp2f(-d * d * c1);
                d = (float)(row1 - ca - 1);   float a11 = f1 * exp2f(-d * d * c1);
                d = (float)(row0 - cb);       float a20 = f0 * exp2f(-d * d * c0);
                d = (float)(row0 - cb - 1);   float a21 = f0 * exp2f(-d * d * c0);
                d = (float)(row1 - cb);       float a30 = f1 * exp2f(-d * d * c1);
                d = (float)(row1 - cb - 1);   float a31 = f1 * exp2f(-d * d * c1);
                uint32_t gh[4], gl[4];
                gh[0] = pkbf2(a00, a01);
                gh[1] = pkbf2(a10, a11);
                gh[2] = pkbf2(a20, a21);
                gh[3] = pkbf2(a30, a31);
                gl[0] = pkbf2(a00 - bf_lo_f(gh[0]), a01 - bf_hi_f(gh[0]));
                gl[1] = pkbf2(a10 - bf_lo_f(gh[1]), a11 - bf_hi_f(gh[1]));
                gl[2] = pkbf2(a20 - bf_lo_f(gh[2]), a21 - bf_hi_f(gh[2]));
                gl[3] = pkbf2(a30 - bf_lo_f(gh[3]), a31 - bf_hi_f(gh[3]));
                const int kb = kk * 32 + t * 4;
#pragma unroll
                for (int nt = 0; nt < 8; nt++) {
                    const int rd = nt * 8 + g;
                    uint32_t bVh[2], bVl[2];
                    bVh[0] = *(uint32_t*)(Vh_ + SWB(rd, kb));
                    bVh[1] = *(uint32_t*)(Vh_ + SWB(rd, kb + 16));
                    bVl[0] = *(uint32_t*)(Vl_ + SWB(rd, kb));
                    bVl[1] = *(uint32_t*)(Vl_ + SWB(rd, kb + 16));
                    mma_bf16(accO[nt], gh, bVh);
                    mma_bf16(accO[nt], gh, bVl);
                    mma_bf16(accO[nt], gl, bVh);
                }
            }
        }
    }

    // ---- scale by gate/Se, store ----
    const float sc0 = gate / rs0, sc1 = gate / rs1;
    float* o0 = Og + ((size_t)(b * 512 + row0) * 8 + h) * 64;
    float* o1 = Og + ((size_t)(b * 512 + row1) * 8 + h) * 64;
#pragma unroll
    for (int nt = 0; nt < 8; nt++) {
        const int dd = nt * 8 + t * 2;
        *(float2*)(o0 + dd) = make_float2(sc0 * accO[nt][0], sc0 * accO[nt][1]);
        *(float2*)(o1 + dd) = make_float2(sc1 * accO[nt][2], sc1 * accO[nt][3]);
    }
}

// ---------------------------------------------------------------------------
extern "C" void kernel_launch(void* const* d_in, const int* in_sizes, int n_in,
                              void* d_out, int out_size) {
    const float* Q   = (const float*)d_in[0];
    const float* K   = (const float*)d_in[1];
    const float* V   = (const float*)d_in[2];
    const float* Sig = (const float*)d_in[3];
    const float* hg  = (const float*)d_in[4];
    float* O = (float*)d_out;
    (void)in_sizes; (void)n_in; (void)out_size;

    cudaFuncSetAttribute(k_fused, cudaFuncAttributeMaxDynamicSharedMemorySize,
                         SMEM_BYTES);

    dim3 gA(4, 128);
    k_fused<<<gA, 256, SMEM_BYTES>>>(Q, K, V, Sig, hg, O);
}

// round 12
// speedup vs baseline: 2.3577x; 1.0209x over previous
#include <cuda_runtime.h>
#include <cuda_bf16.h>
#include <cstdint>

// AnomalyAttention, B=16 L=512 H=8 E=D=64, fp32 in/out. Single fused kernel.
// out = (gate/Se) * [ E.V + G''.V ] per row;
//   E   = exp(Q.K^T/8) causal, 3-term bf16-split HMMA
//   G'' = (Se*og)/(gate*Sg) * 2^{-(l-s)^2 c}, banded +-16, folded post-Se.
// R10/R11: ldmatrix.x4 fragment loads with hoisted swizzle math (-75% LSU
//      issue, -80% address ALU), cp.async-prefetched prior V tiles.
//      (R11 = R10 resubmitted after infra failure; address algebra re-audited.)

// swizzled smem address: 128B rows, XOR row bits into byte bits [4:6]
#define SWB(row, byte) (((row) << 7) + ((byte) ^ (((row) & 7) << 4)))

static __device__ __forceinline__ uint32_t pkbf2(float lo, float hi) {
    uint32_t r;
    asm("cvt.rn.bf16x2.f32 %0, %1, %2;" : "=r"(r) : "f"(hi), "f"(lo));
    return r;
}
static __device__ __forceinline__ float bf_lo_f(uint32_t p) {
    __nv_bfloat162 t = *reinterpret_cast<__nv_bfloat162*>(&p);
    return __bfloat162float(t.x);
}
static __device__ __forceinline__ float bf_hi_f(uint32_t p) {
    __nv_bfloat162 t = *reinterpret_cast<__nv_bfloat162*>(&p);
    return __bfloat162float(t.y);
}
static __device__ __forceinline__ void mma_bf16(float* c, const uint32_t* a,
                                                const uint32_t* b) {
    asm volatile(
        "mma.sync.aligned.m16n8k16.row.col.f32.bf16.bf16.f32 "
        "{%0,%1,%2,%3}, {%4,%5,%6,%7}, {%8,%9}, {%0,%1,%2,%3};"
        : "+f"(c[0]), "+f"(c[1]), "+f"(c[2]), "+f"(c[3])
        : "r"(a[0]), "r"(a[1]), "r"(a[2]), "r"(a[3]), "r"(b[0]), "r"(b[1]));
}
static __device__ __forceinline__ void cpasync16(uint32_t dst, const void* src) {
    asm volatile("cp.async.cg.shared.global [%0], [%1], 16;"
                 :: "r"(dst), "l"(src) : "memory");
}
static __device__ __forceinline__ void ldsm4(uint32_t* r, uint32_t addr) {
    asm volatile("ldmatrix.sync.aligned.m8n8.x4.shared.b16 {%0,%1,%2,%3}, [%4];"
                 : "=r"(r[0]), "=r"(r[1]), "=r"(r[2]), "=r"(r[3]) : "r"(addr));
}

// smem offsets (bytes)
#define OFF_QH 0
#define OFF_QL 16384
#define OFF_KH 32768
#define OFF_KL 40960
#define OFF_VH 49152
#define OFF_VL 57344
#define OFF_KRAW 65536
#define OFF_VRAW 81920
#define SMEM_BYTES 98304

__global__ __launch_bounds__(256)
void k_fused(const float* __restrict__ Qg, const float* __restrict__ Kg,
             const float* __restrict__ Vg, const float* __restrict__ Sig,
             const float* __restrict__ hg, float* __restrict__ Og) {
    extern __shared__ char smc[];
    char* Kh_ = smc + OFF_KH;
    char* Kl_ = smc + OFF_KL;
    char* Vh_ = smc + OFF_VH;
    char* Vl_ = smc + OFF_VL;
    const float* Kraw = (const float*)(smc + OFF_KRAW);
    const float* Vraw = (const float*)(smc + OFF_VRAW);

    uint32_t smb;
    asm("{ .reg .u64 t; cvta.to.shared.u64 t, %1; cvt.u32.u64 %0, t; }"
        : "=r"(smb) : "l"(smc));
    const uint32_t kraw32 = smb + OFF_KRAW;
    const uint32_t vraw32 = smb + OFF_VRAW;

    const int rtile = 3 - blockIdx.x;  // heavy blocks first
    const int bh = blockIdx.y;
    const int b = bh >> 3, h = bh & 7;
    const int tid = threadIdx.x;
    const int wid = tid >> 5, lane = tid & 31;
    const int g = lane >> 2, t = lane & 3;
    const int lbase = rtile * 128;
    const int wr = wid * 16;
    const int row0 = lbase + wr + g, row1 = row0 + 8;
    const int wlast = lbase + wr + 15;

    // ---- ldmatrix per-lane base addresses (swizzle hoisted) ----
    // A operand (Q): m0 rows wr+0..7 @kb, m1 rows +8 @kb, m2/m3 same @kb+16.
    const int rowq = wr + (lane & 15);
    const uint32_t keyq = (rowq & 7) << 4;
    const uint32_t qbase = smb + (rowq << 7) + ((lane & 16) ^ (keyq & 0x10));
    const uint32_t qx = keyq & 0x60;
    // B operand (K/V): per pair p: m0/m1 rows 16p+0..7 @kb/kb+16, m2/m3 rows +8.
    const int rowb = (lane & 7) + ((lane & 16) >> 1);
    const uint32_t keyb = (lane & 7) << 4;
    const uint32_t bbase = smb + (rowb << 7) + (((lane & 8) << 1) ^ (keyb & 0x10));
    const uint32_t bx = keyb & 0x60;

    // ---- per-lane prior constants ----
    float c0, c1, iSg0, iSg1;
    {
#pragma unroll
        for (int rr_ = 0; rr_ < 2; rr_++) {
            int l = rr_ ? row1 : row0;
            float x = Sig[((size_t)(b * 512 + l)) * 8 + h];
            float sgm = 1.f / (1.f + __expf(-5.f * x)) + 1e-5f;
            float sv = exp2f(sgm * 1.5849625007211562f) - 1.f;  // 3^sgm - 1
            float c = 1.4426950408889634f / (2.f * sv * sv);
            int wmax = (int)sqrtf(24.f / c);
            if (wmax > 16) wmax = 16;
            float gg = 1.f, rq = exp2f(-c), q = rq * rq, S = 1.f;
            for (int w = 1; w <= wmax; w++) {
                gg *= rq; rq *= q;
                if (l - w >= 0)  S += gg;
                if (l + w < 512) S += gg;
            }
            if (rr_) { c1 = c; iSg1 = 1.f / S; }
            else     { c0 = c; iSg0 = 1.f / S; }
        }
    }

    // ---- stage Q once: bf16 hi/lo split, swizzled ----
    {
        const float* Qb = Qg + ((size_t)(b * 512 + lbase) * 8 + h) * 64;
        char* Qh_ = smc + OFF_QH;
        char* Ql_ = smc + OFF_QL;
        for (int idx = tid; idx < 2048; idx += 256) {
            int l = idx >> 4, e4 = (idx & 15) << 2;
            float4 v = *(const float4*)(Qb + l * 512 + e4);
            uint32_t h0 = pkbf2(v.x, v.y), h1 = pkbf2(v.z, v.w);
            uint32_t l0 = pkbf2(v.x - bf_lo_f(h0), v.y - bf_hi_f(h0));
            uint32_t l1 = pkbf2(v.z - bf_lo_f(h1), v.w - bf_hi_f(h1));
            int sa = SWB(l, e4 * 2);
            *(uint2*)(Qh_ + sa) = make_uint2(h0, h1);
            *(uint2*)(Ql_ + sa) = make_uint2(l0, l1);
        }
    }

    float accO[8][4];
#pragma unroll
    for (int nt = 0; nt < 8; nt++)
#pragma unroll
        for (int i = 0; i < 4; i++) accO[nt][i] = 0.f;
    float rs0 = 0.f, rs1 = 0.f;

    const int ntiles = 2 * rtile + 2;

    // prior tile order (first is resident after the main loop)
    int pts[4];
    int np = 0;
    pts[np++] = 2 * rtile + 1;
    if (2 * rtile - 1 >= 0) pts[np++] = 2 * rtile - 1;
    pts[np++] = 2 * rtile;
    if (2 * rtile + 2 <= 7) pts[np++] = 2 * rtile + 2;

    // prefetch tile 0
    {
        const float* Kb = Kg + ((size_t)(b * 512) * 8 + h) * 64;
        const float* Vb = Vg + ((size_t)(b * 512) * 8 + h) * 64;
        for (int idx = tid; idx < 1024; idx += 256) {
            int s = idx >> 4, cc = (idx & 15) << 2;
            cpasync16(kraw32 + idx * 16, Kb + s * 512 + cc);
            cpasync16(vraw32 + idx * 16, Vb + s * 512 + cc);
        }
        asm volatile("cp.async.commit_group;" ::: "memory");
    }

    for (int st = 0; st < ntiles; st++) {
        const int s0 = st * 64;
        asm volatile("cp.async.wait_group 0;" ::: "memory");
        __syncthreads();

        // ---- convert raw -> split smem ----
        for (int idx = tid; idx < 1024; idx += 256) {
            int s = idx >> 4, e4 = (idx & 15) << 2;
            float4 v = *(const float4*)(Kraw + idx * 4);
            uint32_t h0 = pkbf2(v.x, v.y), h1 = pkbf2(v.z, v.w);
            uint32_t l0 = pkbf2(v.x - bf_lo_f(h0), v.y - bf_hi_f(h0));
            uint32_t l1 = pkbf2(v.z - bf_lo_f(h1), v.w - bf_hi_f(h1));
            int sa = SWB(s, e4 * 2);
            *(uint2*)(Kh_ + sa) = make_uint2(h0, h1);
            *(uint2*)(Kl_ + sa) = make_uint2(l0, l1);
        }
        for (int idx = tid; idx < 512; idx += 256) {
            int sp = idx >> 4, dq = idx & 15;
            int s = sp * 2, d4 = dq * 4;
            float4 v0 = *(const float4*)(Vraw + s * 64 + d4);
            float4 v1 = *(const float4*)(Vraw + (s + 1) * 64 + d4);
            float a0[4] = {v0.x, v0.y, v0.z, v0.w};
            float a1[4] = {v1.x, v1.y, v1.z, v1.w};
#pragma unroll
            for (int j = 0; j < 4; j++) {
                uint32_t hp = pkbf2(a0[j], a1[j]);
                uint32_t lp = pkbf2(a0[j] - bf_lo_f(hp), a1[j] - bf_hi_f(hp));
                int sa = SWB(d4 + j, sp * 4);
                *(uint32_t*)(Vh_ + sa) = hp;
                *(uint32_t*)(Vl_ + sa) = lp;
            }
        }
        __syncthreads();

        // ---- prefetch next tile (or first non-resident prior tile) ----
        if (st + 1 < ntiles) {
            const int sn = (st + 1) * 64;
            const float* Kb = Kg + ((size_t)(b * 512 + sn) * 8 + h) * 64;
            const float* Vb = Vg + ((size_t)(b * 512 + sn) * 8 + h) * 64;
            for (int idx = tid; idx < 1024; idx += 256) {
                int s = idx >> 4, cc = (idx & 15) << 2;
                cpasync16(kraw32 + idx * 16, Kb + s * 512 + cc);
                cpasync16(vraw32 + idx * 16, Vb + s * 512 + cc);
            }
            asm volatile("cp.async.commit_group;" ::: "memory");
        } else {
            const int sn = pts[1] * 64;
            const float* Vb = Vg + ((size_t)(b * 512 + sn) * 8 + h) * 64;
            for (int idx = tid; idx < 1024; idx += 256) {
                int s = idx >> 4, cc = (idx & 15) << 2;
                cpasync16(vraw32 + idx * 16, Vb + s * 512 + cc);
            }
            asm volatile("cp.async.commit_group;" ::: "memory");
        }

        if (s0 > wlast) continue;  // whole tile masked for this warp

        // ---- QK: S[16 l][64 s] via ldmatrix + m16n8k16 ----
        float accS[8][4];
#pragma unroll
        for (int nt = 0; nt < 8; nt++)
#pragma unroll
            for (int i = 0; i < 4; i++) accS[nt][i] = 0.f;

#pragma unroll
        for (int k = 0; k < 4; k++) {
            const uint32_t koq = ((uint32_t)(k << 5)) ^ qx;
            const uint32_t kob = ((uint32_t)(k << 5)) ^ bx;
            uint32_t aQh[4], aQl[4];
            ldsm4(aQh, qbase + OFF_QH + koq);
            ldsm4(aQl, qbase + OFF_QL + koq);
#pragma unroll
            for (int p = 0; p < 4; p++) {
                if (s0 + p * 16 > wlast) continue;       // warp-uniform
                uint32_t bKh[4], bKl[4];
                ldsm4(bKh, bbase + OFF_KH + (p << 11) + kob);
                ldsm4(bKl, bbase + OFF_KL + (p << 11) + kob);
                mma_bf16(accS[2 * p], aQh, bKh);
                mma_bf16(accS[2 * p], aQh, bKl);
                mma_bf16(accS[2 * p], aQl, bKh);
                if (s0 + p * 16 + 8 <= wlast) {          // warp-uniform
                    mma_bf16(accS[2 * p + 1], aQh, bKh + 2);
                    mma_bf16(accS[2 * p + 1], aQh, bKl + 2);
                    mma_bf16(accS[2 * p + 1], aQl, bKh + 2);
                }
            }
        }

        // ---- mask + exp, row sums ----
#pragma unroll
        for (int nt = 0; nt < 8; nt++) {
            if (s0 + nt * 8 > wlast) continue;
            const int c0_ = s0 + nt * 8 + t * 2;
            float e0 = (c0_     <= row0) ? __expf(accS[nt][0] * 0.125f) : 0.f;
            float e1 = (c0_ + 1 <= row0) ? __expf(accS[nt][1] * 0.125f) : 0.f;
            float e2 = (c0_     <= row1) ? __expf(accS[nt][2] * 0.125f) : 0.f;
            float e3 = (c0_ + 1 <= row1) ? __expf(accS[nt][3] * 0.125f) : 0.f;
            rs0 += e0 + e1;
            rs1 += e2 + e3;
            accS[nt][0] = e0; accS[nt][1] = e1;
            accS[nt][2] = e2; accS[nt][3] = e3;
        }

        // ---- EV: O += E.V ----
#pragma unroll
        for (int kk = 0; kk < 4; kk++) {
            if (s0 + kk * 16 > wlast) continue;          // warp-uniform
            const int n0 = 2 * kk, n1 = 2 * kk + 1;
            uint32_t eh[4], el[4];
            eh[0] = pkbf2(accS[n0][0], accS[n0][1]);
            eh[1] = pkbf2(accS[n0][2], accS[n0][3]);
            eh[2] = pkbf2(accS[n1][0], accS[n1][1]);
            eh[3] = pkbf2(accS[n1][2], accS[n1][3]);
            el[0] = pkbf2(accS[n0][0] - bf_lo_f(eh[0]), accS[n0][1] - bf_hi_f(eh[0]));
            el[1] = pkbf2(accS[n0][2] - bf_lo_f(eh[1]), accS[n0][3] - bf_hi_f(eh[1]));
            el[2] = pkbf2(accS[n1][0] - bf_lo_f(eh[2]), accS[n1][1] - bf_hi_f(eh[2]));
            el[3] = pkbf2(accS[n1][2] - bf_lo_f(eh[3]), accS[n1][3] - bf_hi_f(eh[3]));
            const uint32_t kob = ((uint32_t)(kk << 5)) ^ bx;
#pragma unroll
            for (int p = 0; p < 4; p++) {
                uint32_t bVh[4], bVl[4];
                ldsm4(bVh, bbase + OFF_VH + (p << 11) + kob);
                ldsm4(bVl, bbase + OFF_VL + (p << 11) + kob);
                mma_bf16(accO[2 * p], eh, bVh);
                mma_bf16(accO[2 * p], eh, bVl);
                mma_bf16(accO[2 * p], el, bVh);
                mma_bf16(accO[2 * p + 1], eh, bVh + 2);
                mma_bf16(accO[2 * p + 1], eh, bVl + 2);
                mma_bf16(accO[2 * p + 1], el, bVh + 2);
            }
        }
    }

    // ---- row-sum reduce (Se now known) ----
    rs0 += __shfl_xor_sync(0xFFFFFFFFu, rs0, 1);
    rs0 += __shfl_xor_sync(0xFFFFFFFFu, rs0, 2);
    rs1 += __shfl_xor_sync(0xFFFFFFFFu, rs1, 1);
    rs1 += __shfl_xor_sync(0xFFFFFFFFu, rs1, 2);

    const float gate = 1.f / (1.f + __expf(-hg[h]));
    const float og = 1.f - gate;
    const float f0 = rs0 * og * iSg0 / gate;
    const float f1 = rs1 * og * iSg1 / gate;

    // ---- prior phase: accO += G''.V; tile 0 resident, rest prefetched ----
    {
        const int wb0 = lbase + wr - 16;
        const int wb1 = lbase + wr + 15 + 16;

        for (int pi = 0; pi < np; pi++) {
            const int s0 = pts[pi] * 64;
            if (pi > 0) {
                asm volatile("cp.async.wait_group 0;" ::: "memory");
                __syncthreads();
                for (int idx = tid; idx < 512; idx += 256) {
                    int sp = idx >> 4, dq = idx & 15;
                    int s = sp * 2, d4 = dq * 4;
                    float4 v0 = *(const float4*)(Vraw + s * 64 + d4);
                    float4 v1 = *(const float4*)(Vraw + (s + 1) * 64 + d4);
                    float a0[4] = {v0.x, v0.y, v0.z, v0.w};
                    float a1[4] = {v1.x, v1.y, v1.z, v1.w};
#pragma unroll
                    for (int j = 0; j < 4; j++) {
                        uint32_t hp = pkbf2(a0[j], a1[j]);
                        uint32_t lp = pkbf2(a0[j] - bf_lo_f(hp), a1[j] - bf_hi_f(hp));
                        int sa = SWB(d4 + j, sp * 4);
                        *(uint32_t*)(Vh_ + sa) = hp;
                        *(uint32_t*)(Vl_ + sa) = lp;
                    }
                }
                __syncthreads();
                if (pi + 1 < np) {
                    const int sn = pts[pi + 1] * 64;
                    const float* Vb = Vg + ((size_t)(b * 512 + sn) * 8 + h) * 64;
                    for (int idx = tid; idx < 1024; idx += 256) {
                        int s = idx >> 4, cc = (idx & 15) << 2;
                        cpasync16(vraw32 + idx * 16, Vb + s * 512 + cc);
                    }
                    asm volatile("cp.async.commit_group;" ::: "memory");
                }
            }

#pragma unroll
            for (int kk = 0; kk < 4; kk++) {
                const int ks0 = s0 + kk * 16;
                if (ks0 + 15 < wb0 || ks0 > wb1) continue;  // warp-uniform
                const int ca = ks0 + 2 * t, cb = ca + 8;
                float d;
                d = (float)(row0 - ca);       float a00 = f0 * exp2f(-d * d * c0);
                d = (float)(row0 - ca - 1);   float a01 = f0 * exp2f(-d * d * c0);
                d = (float)(row1 - ca);       float a10 = f1 * exp2f(-d * d * c1);
                d = (float)(row1 - ca - 1);   float a11 = f1 * exp2f(-d * d * c1);
                d = (float)(row0 - cb);       float a20 = f0 * exp2f(-d * d * c0);
                d = (float)(row0 - cb - 1);   float a21 = f0 * exp2f(-d * d * c0);
                d = (float)(row1 - cb);       float a30 = f1 * exp2f(-d * d * c1);
                d = (float)(row1 - cb - 1);   float a31 = f1 * exp2f(-d * d * c1);
                uint32_t gh[4], gl[4];
                gh[0] = pkbf2(a00, a01);
                gh[1] = pkbf2(a10, a11);
                gh[2] = pkbf2(a20, a21);
                gh[3] = pkbf2(a30, a31);
                gl[0] = pkbf2(a00 - bf_lo_f(gh[0]), a01 - bf_hi_f(gh[0]));
                gl[1] = pkbf2(a10 - bf_lo_f(gh[1]), a11 - bf_hi_f(gh[1]));
                gl[2] = pkbf2(a20 - bf_lo_f(gh[2]), a21 - bf_hi_f(gh[2]));
                gl[3] = pkbf2(a30 - bf_lo_f(gh[3]), a31 - bf_hi_f(gh[3]));
                const uint32_t kob = ((uint32_t)(kk << 5)) ^ bx;
#pragma unroll
                for (int p = 0; p < 4; p++) {
                    uint32_t bVh[4], bVl[4];
                    ldsm4(bVh, bbase + OFF_VH + (p << 11) + kob);
                    ldsm4(bVl, bbase + OFF_VL + (p << 11) + kob);
                    mma_bf16(accO[2 * p], gh, bVh);
                    mma_bf16(accO[2 * p], gh, bVl);
                    mma_bf16(accO[2 * p], gl, bVh);
                    mma_bf16(accO[2 * p + 1], gh, bVh + 2);
                    mma_bf16(accO[2 * p + 1], gh, bVl + 2);
                    mma_bf16(accO[2 * p + 1], gl, bVh + 2);
                }
            }
        }
    }

    // ---- scale by gate/Se, store ----
    const float sc0 = gate / rs0, sc1 = gate / rs1;
    float* o0 = Og + ((size_t)(b * 512 + row0) * 8 + h) * 64;
    float* o1 = Og + ((size_t)(b * 512 + row1) * 8 + h) * 64;
#pragma unroll
    for (int nt = 0; nt < 8; nt++) {
        const int dd = nt * 8 + t * 2;
        *(float2*)(o0 + dd) = make_float2(sc0 * accO[nt][0], sc0 * accO[nt][1]);
        *(float2*)(o1 + dd) = make_float2(sc1 * accO[nt][2], sc1 * accO[nt][3]);
    }
}

// ---------------------------------------------------------------------------
extern "C" void kernel_launch(void* const* d_in, const int* in_sizes, int n_in,
                              void* d_out, int out_size) {
    const float* Q   = (const float*)d_in[0];
    const float* K   = (const float*)d_in[1];
    const float* V   = (const float*)d_in[2];
    const float* Sig = (const float*)d_in[3];
    const float* hg  = (const float*)d_in[4];
    float* O = (float*)d_out;
    (void)in_sizes; (void)n_in; (void)out_size;

    cudaFuncSetAttribute(k_fused, cudaFuncAttributeMaxDynamicSharedMemorySize,
                         SMEM_BYTES);

    dim3 gA(4, 128);
    k_fused<<<gA, 256, SMEM_BYTES>>>(Q, K, V, Sig, hg, O);
}